// round 12
// baseline (speedup 1.0000x reference)
#include <cuda_runtime.h>
#include <cuda_bf16.h>
#include <math.h>
#include <stdint.h>

#define BB   2
#define SEQ  2048
#define CH   768
#define NH   12
#define HD   64
#define MROWS (BB*SEQ)      // 4096
#define QKVN  (3*CH)        // 2304
#define SSTR  40            // gemm smem stride (bf16)
#define KSTR  72            // flash smem stride (bf16)

// ---- device global scratch ----
__device__ __align__(16) __nv_bfloat16 g_xh[MROWS*CH],  g_xl[MROWS*CH];
__device__ __align__(16) __nv_bfloat16 g_wqh[QKVN*CH],  g_wql[QKVN*CH];
__device__ __align__(16) __nv_bfloat16 g_wph[CH*CH],    g_wpl[CH*CH];
__device__ __align__(16) __nv_bfloat16 g_qh[BB*NH*SEQ*HD], g_ql[BB*NH*SEQ*HD];
__device__ __align__(16) __nv_bfloat16 g_kh[BB*NH*SEQ*HD], g_kl[BB*NH*SEQ*HD];
__device__ __align__(16) __nv_bfloat16 g_vth[BB*NH*HD*SEQ], g_vtl[BB*NH*HD*SEQ];
__device__ __align__(16) __nv_bfloat16 g_ctxh[MROWS*CH], g_ctxl[MROWS*CH];
__device__ __align__(16) float2 g_rope[SEQ * 32];   // [n][dd/2] = (cos, sin)

// ===========================================================================
// helpers
// ===========================================================================
__device__ __forceinline__ uint32_t smem_to_u32(const void* p) {
    uint32_t a;
    asm("{ .reg .u64 t; cvta.to.shared.u64 t, %1; cvt.u32.u64 %0, t; }"
        : "=r"(a) : "l"(p));
    return a;
}
#define CP16(s, g) \
    asm volatile("cp.async.cg.shared.global [%0], [%1], 16;" :: "r"(s), "l"(g))
#define CP_COMMIT() asm volatile("cp.async.commit_group;" ::: "memory")
#define CP_WAIT1()  asm volatile("cp.async.wait_group 1;" ::: "memory")
#define CP_WAIT0()  asm volatile("cp.async.wait_group 0;" ::: "memory")

__device__ __forceinline__ void mma16816(float* c, const uint32_t* a,
                                         const uint32_t* b) {
    asm volatile(
        "mma.sync.aligned.m16n8k16.row.col.f32.bf16.bf16.f32 "
        "{%0,%1,%2,%3}, {%4,%5,%6,%7}, {%8,%9}, {%0,%1,%2,%3};"
        : "+f"(c[0]), "+f"(c[1]), "+f"(c[2]), "+f"(c[3])
        : "r"(a[0]), "r"(a[1]), "r"(a[2]), "r"(a[3]), "r"(b[0]), "r"(b[1]));
}
__device__ __forceinline__ void ldsm4(uint32_t r[4], uint32_t a) {
    asm volatile("ldmatrix.sync.aligned.m8n8.x4.shared.b16 {%0,%1,%2,%3}, [%4];"
        : "=r"(r[0]), "=r"(r[1]), "=r"(r[2]), "=r"(r[3]) : "r"(a));
}
__device__ __forceinline__ void splitpair(float x, float y,
                                          uint32_t& hi, uint32_t& lo) {
    __nv_bfloat16 hx = __float2bfloat16_rn(x), hy = __float2bfloat16_rn(y);
    __nv_bfloat162 h = __halves2bfloat162(hx, hy);
    hi = *(uint32_t*)&h;
    __nv_bfloat162 l = __floats2bfloat162_rn(x - __bfloat162float(hx),
                                             y - __bfloat162float(hy));
    lo = *(uint32_t*)&l;
}
// per-lane byte offsets for ldmatrix.x4 fragment loads
__device__ __forceinline__ uint32_t aoff_lane(int lane, int stride) {
    return (uint32_t)((((lane & 7) + ((lane >> 3) & 1) * 8) * stride +
                       ((lane >> 4) << 3)) * 2);
}
__device__ __forceinline__ uint32_t boff_lane(int lane, int stride) {
    return (uint32_t)((((lane & 7) + ((lane >> 4) << 3)) * stride +
                       ((lane >> 3) & 1) * 8) * 2);
}

// ---------------------------------------------------------------------------
// Pre-passes
// ---------------------------------------------------------------------------
__global__ void split_kernel(const float* __restrict__ src,
                             __nv_bfloat16* __restrict__ h,
                             __nv_bfloat16* __restrict__ l, int n4)
{
    int i = blockIdx.x * blockDim.x + threadIdx.x;
    if (i < n4) {
        float4 v = ((const float4*)src)[i];
        uint2 hi, lo;
        splitpair(v.x, v.y, hi.x, lo.x);
        splitpair(v.z, v.w, hi.y, lo.y);
        ((uint2*)h)[i] = hi;
        ((uint2*)l)[i] = lo;
    }
}
__global__ void rope_kernel()
{
    int i = blockIdx.x * blockDim.x + threadIdx.x;
    if (i < SEQ * 32) {
        int n = i >> 5, dd2 = i & 31;
        float freq = powf(10000.f, -((float)(2 * dd2)) / 64.f);
        float s, c;
        sincosf((float)n * freq, &s, &c);
        g_rope[i] = make_float2(c, s);
    }
}

// ---------------------------------------------------------------------------
// GEMM core (unchanged from R11)
// ---------------------------------------------------------------------------
#define ARRG  (128 * SSTR)
#define ARRGB (ARRG * 2)
#define STAGEGB (4 * ARRGB)

__device__ __forceinline__ void gemm_issue(
    uint32_t sb, const __nv_bfloat16* Ah, const __nv_bfloat16* Al,
    const __nv_bfloat16* Bh, const __nv_bfloat16* Bl,
    int K, int m0, int c0, int k0, int tid)
{
#pragma unroll
    for (int t = 0; t < 2; t++) {
        int f = tid + t * 256, r = f >> 2, c = (f & 3) * 8;
        uint32_t off = (uint32_t)(r * (SSTR * 2) + c * 2);
        CP16(sb + off,             &Ah[(size_t)(m0 + r) * K + k0 + c]);
        CP16(sb + ARRGB + off,     &Al[(size_t)(m0 + r) * K + k0 + c]);
        CP16(sb + 2 * ARRGB + off, &Bh[(size_t)(c0 + r) * K + k0 + c]);
        CP16(sb + 3 * ARRGB + off, &Bl[(size_t)(c0 + r) * K + k0 + c]);
    }
    CP_COMMIT();
}

__device__ __forceinline__ void gemm_bf16(
    const __nv_bfloat16* __restrict__ Ah, const __nv_bfloat16* __restrict__ Al,
    const __nv_bfloat16* __restrict__ Bh, const __nv_bfloat16* __restrict__ Bl,
    int K, int m0, int c0, float acc[4][4][4])
{
    extern __shared__ __nv_bfloat16 smp[];
    const uint32_t sb0 = smem_to_u32(smp);
    const int tid = threadIdx.x, lane = tid & 31, wid = tid >> 5;
    const int wm = (wid >> 2) * 64, wn = (wid & 3) * 32;
    const uint32_t ao = aoff_lane(lane, SSTR);
    const uint32_t bo = boff_lane(lane, SSTR);

#pragma unroll
    for (int i = 0; i < 4; i++)
#pragma unroll
        for (int j = 0; j < 4; j++)
#pragma unroll
            for (int r = 0; r < 4; r++) acc[i][j][r] = 0.f;

    const int nck = K / 32;
    gemm_issue(sb0, Ah, Al, Bh, Bl, K, m0, c0, 0, tid);

    for (int ck = 0; ck < nck; ck++) {
        if (ck + 1 < nck) {
            gemm_issue(sb0 + ((ck + 1) & 1) * STAGEGB, Ah, Al, Bh, Bl,
                       K, m0, c0, (ck + 1) * 32, tid);
            CP_WAIT1();
        } else {
            CP_WAIT0();
        }
        __syncthreads();

        const uint32_t st = sb0 + (ck & 1) * STAGEGB;
        const uint32_t cAh = st, cAl = st + ARRGB;
        const uint32_t cBh = st + 2 * ARRGB, cBl = st + 3 * ARRGB;

#pragma unroll
        for (int ks = 0; ks < 32; ks += 16) {
            uint32_t ah[4][4], al[4][4];
#pragma unroll
            for (int mf = 0; mf < 4; mf++) {
                uint32_t ra = (uint32_t)(((wm + mf * 16) * SSTR + ks) * 2) + ao;
                ldsm4(ah[mf], cAh + ra);
                ldsm4(al[mf], cAl + ra);
            }
#pragma unroll
            for (int p = 0; p < 2; p++) {
                uint32_t bh4[4], bl4[4];
                uint32_t rb = (uint32_t)(((wn + p * 16) * SSTR + ks) * 2) + bo;
                ldsm4(bh4, cBh + rb);
                ldsm4(bl4, cBl + rb);
#pragma unroll
                for (int sub = 0; sub < 2; sub++) {
                    const int nf = p * 2 + sub;
#pragma unroll
                    for (int mf = 0; mf < 4; mf++) {
                        mma16816(acc[mf][nf], ah[mf], &bh4[sub * 2]);
                        mma16816(acc[mf][nf], ah[mf], &bl4[sub * 2]);
                        mma16816(acc[mf][nf], al[mf], &bh4[sub * 2]);
                    }
                }
            }
        }
        __syncthreads();
    }
}

// ---------------------------------------------------------------------------
// QKV GEMM + scale/RoPE(table) epilogue (unchanged)
// ---------------------------------------------------------------------------
__global__ __launch_bounds__(256, 2) void qkv_mma_kernel()
{
    const int m0 = blockIdx.y * 128, c0 = blockIdx.x * 128;
    float acc[4][4][4];
    gemm_bf16(g_xh, g_xl, g_wqh, g_wql, CH, m0, c0, acc);

    const int tid = threadIdx.x, lane = tid & 31, wid = tid >> 5;
    const int wm = (wid >> 2) * 64, wn = (wid & 3) * 32;
    const int g = lane >> 2, t2 = (lane & 3) * 2;

    const int which = (c0 + wn) / CH;
    const float sc = (which == 0) ? 0.125f : 1.0f;

#pragma unroll
    for (int nf = 0; nf < 4; nf++) {
        const int col = c0 + wn + nf * 8 + t2;
        const int h   = (col % CH) >> 6;
        const int dd  = col & 63;                 // even
#pragma unroll
        for (int mf = 0; mf < 4; mf++) {
#pragma unroll
            for (int rr = 0; rr < 2; rr++) {
                const int m = m0 + wm + mf * 16 + g + rr * 8;
                const int b = m >> 11, n = m & 2047;
                const int bh = b * NH + h;
                float x0 = acc[mf][nf][rr * 2], x1 = acc[mf][nf][rr * 2 + 1];
                if (which == 2) {
                    __nv_bfloat16 h0 = __float2bfloat16_rn(x0);
                    __nv_bfloat16 h1 = __float2bfloat16_rn(x1);
                    size_t o0 = ((size_t)bh * HD + dd) * SEQ + n;
                    g_vth[o0]       = h0;
                    g_vth[o0 + SEQ] = h1;
                    g_vtl[o0]       = __float2bfloat16_rn(x0 - __bfloat162float(h0));
                    g_vtl[o0 + SEQ] = __float2bfloat16_rn(x1 - __bfloat162float(h1));
                } else {
                    const float2 cs = g_rope[(n << 5) + (dd >> 1)];
                    x0 *= sc; x1 *= sc;
                    uint32_t hi, lo;
                    splitpair(x0 * cs.x - x1 * cs.y, x1 * cs.x + x0 * cs.y, hi, lo);
                    size_t o = ((size_t)bh * SEQ + n) * HD + dd;
                    if (which == 0) {
                        *(uint32_t*)&g_qh[o] = hi; *(uint32_t*)&g_ql[o] = lo;
                    } else {
                        *(uint32_t*)&g_kh[o] = hi; *(uint32_t*)&g_kl[o] = lo;
                    }
                }
            }
        }
    }
}

// ---------------------------------------------------------------------------
// Flash attention: NOW 128 threads / 64 q-rows per CTA, 3 CTAs/SM.
// Per-warp work identical to R11 (16 rows x 64 keys).
// ---------------------------------------------------------------------------
#define ARRF  (64 * KSTR)
#define ARRFB (ARRF * 2)
#define STAGEFB (4 * ARRFB)

__device__ __forceinline__ void flash_issue(uint32_t sb, int bh, int j0, int tid)
{
#pragma unroll
    for (int t = 0; t < 4; t++) {
        int f = tid + t * 128, r = f >> 3, c8 = (f & 7) * 8;
        uint32_t off = (uint32_t)(r * (KSTR * 2) + c8 * 2);
        CP16(sb + off,             &g_kh[((size_t)bh * SEQ + j0 + r) * HD + c8]);
        CP16(sb + ARRFB + off,     &g_kl[((size_t)bh * SEQ + j0 + r) * HD + c8]);
        CP16(sb + 2 * ARRFB + off, &g_vth[((size_t)bh * HD + r) * SEQ + j0 + c8]);
        CP16(sb + 3 * ARRFB + off, &g_vtl[((size_t)bh * HD + r) * SEQ + j0 + c8]);
    }
    CP_COMMIT();
}

__global__ __launch_bounds__(128, 3) void flash_mma_kernel()
{
    extern __shared__ __nv_bfloat16 fsm[];
    const uint32_t sb0 = smem_to_u32(fsm);

    const int tid = threadIdx.x, lane = tid & 31, wid = tid >> 5;  // wid 0..3
    const int g = lane >> 2, t2 = (lane & 3) * 2;
    const int bh = blockIdx.y;
    const int q0 = blockIdx.x * 64;
    const int qrow = q0 + wid * 16;
    const uint32_t bo = boff_lane(lane, KSTR);

    // Q fragments (hi/lo), register-resident
    uint32_t qa[2][4][4];
#pragma unroll
    for (int hl = 0; hl < 2; hl++) {
        const __nv_bfloat16* Qp = hl ? g_ql : g_qh;
        const size_t r0 = ((size_t)bh * SEQ + qrow + g) * HD;
        const size_t r1 = ((size_t)bh * SEQ + qrow + g + 8) * HD;
#pragma unroll
        for (int t = 0; t < 4; t++) {
            qa[hl][t][0] = *(const uint32_t*)&Qp[r0 + t * 16 + t2];
            qa[hl][t][1] = *(const uint32_t*)&Qp[r1 + t * 16 + t2];
            qa[hl][t][2] = *(const uint32_t*)&Qp[r0 + t * 16 + t2 + 8];
            qa[hl][t][3] = *(const uint32_t*)&Qp[r1 + t * 16 + t2 + 8];
        }
    }

    float o[8][4];
#pragma unroll
    for (int nf = 0; nf < 8; nf++)
#pragma unroll
        for (int r = 0; r < 4; r++) o[nf][r] = 0.f;
    float mi[2] = {-1e30f, -1e30f}, li[2] = {0.f, 0.f};

    flash_issue(sb0, bh, 0, tid);

    for (int jt = 0; jt < SEQ / 64; jt++) {
        if (jt + 1 < SEQ / 64) {
            flash_issue(sb0 + ((jt + 1) & 1) * STAGEFB, bh, (jt + 1) * 64, tid);
            CP_WAIT1();
        } else {
            CP_WAIT0();
        }
        __syncthreads();

        const uint32_t st = sb0 + (jt & 1) * STAGEFB;
        const uint32_t cKh = st, cKl = st + ARRFB;
        const uint32_t cVh = st + 2 * ARRFB, cVl = st + 3 * ARRFB;

        // S = Q.K^T
        float s[8][4];
#pragma unroll
        for (int nf = 0; nf < 8; nf++)
#pragma unroll
            for (int r = 0; r < 4; r++) s[nf][r] = 0.f;
#pragma unroll
        for (int t = 0; t < 4; t++) {
#pragma unroll
            for (int p = 0; p < 4; p++) {
                uint32_t kh4[4], kl4[4];
                uint32_t rb = (uint32_t)((p * 16 * KSTR + t * 16) * 2) + bo;
                ldsm4(kh4, cKh + rb);
                ldsm4(kl4, cKl + rb);
#pragma unroll
                for (int sub = 0; sub < 2; sub++) {
                    const int nf = p * 2 + sub;
                    mma16816(s[nf], qa[0][t], &kh4[sub * 2]);
                    mma16816(s[nf], qa[0][t], &kl4[sub * 2]);
                    mma16816(s[nf], qa[1][t], &kh4[sub * 2]);
                }
            }
        }

        // online softmax (rows g, g+8)
#pragma unroll
        for (int rr = 0; rr < 2; rr++) {
            float mx = -1e30f;
#pragma unroll
            for (int nf = 0; nf < 8; nf++)
                mx = fmaxf(mx, fmaxf(s[nf][rr * 2], s[nf][rr * 2 + 1]));
            mx = fmaxf(mx, __shfl_xor_sync(0xffffffffu, mx, 1));
            mx = fmaxf(mx, __shfl_xor_sync(0xffffffffu, mx, 2));
            float mnew = fmaxf(mi[rr], mx);
            float alpha = __expf(mi[rr] - mnew);
            mi[rr] = mnew;
            float sum = 0.f;
#pragma unroll
            for (int nf = 0; nf < 8; nf++) {
                float p0 = __expf(s[nf][rr * 2]     - mnew);
                float p1 = __expf(s[nf][rr * 2 + 1] - mnew);
                s[nf][rr * 2] = p0; s[nf][rr * 2 + 1] = p1;
                sum += p0 + p1;
            }
            sum += __shfl_xor_sync(0xffffffffu, sum, 1);
            sum += __shfl_xor_sync(0xffffffffu, sum, 2);
            li[rr] = li[rr] * alpha + sum;
#pragma unroll
            for (int nf = 0; nf < 8; nf++) {
                o[nf][rr * 2] *= alpha; o[nf][rr * 2 + 1] *= alpha;
            }
        }

        // O += P.V
#pragma unroll
        for (int t = 0; t < 4; t++) {
            uint32_t ph[4], pl[4];
            splitpair(s[2*t][0],   s[2*t][1],   ph[0], pl[0]);
            splitpair(s[2*t][2],   s[2*t][3],   ph[1], pl[1]);
            splitpair(s[2*t+1][0], s[2*t+1][1], ph[2], pl[2]);
            splitpair(s[2*t+1][2], s[2*t+1][3], ph[3], pl[3]);
#pragma unroll
            for (int p = 0; p < 4; p++) {
                uint32_t vh4[4], vl4[4];
                uint32_t rb = (uint32_t)((p * 16 * KSTR + t * 16) * 2) + bo;
                ldsm4(vh4, cVh + rb);
                ldsm4(vl4, cVl + rb);
#pragma unroll
                for (int sub = 0; sub < 2; sub++) {
                    const int nf = p * 2 + sub;
                    mma16816(o[nf], ph, &vh4[sub * 2]);
                    mma16816(o[nf], ph, &vl4[sub * 2]);
                    mma16816(o[nf], pl, &vh4[sub * 2]);
                }
            }
        }
        __syncthreads();
    }

    // epilogue: normalize, split, write ctx hi/lo bf16 [B][N][C]
    const int b = bh / NH, h = bh % NH;
    const float inv0 = 1.f / li[0], inv1 = 1.f / li[1];
#pragma unroll
    for (int rr = 0; rr < 2; rr++) {
        const int n = qrow + g + rr * 8;
        const float inv = rr ? inv1 : inv0;
        const size_t base = ((size_t)b * SEQ + n) * CH + h * HD;
#pragma unroll
        for (int nf = 0; nf < 8; nf++) {
            uint32_t hi, lo;
            splitpair(o[nf][rr * 2] * inv, o[nf][rr * 2 + 1] * inv, hi, lo);
            *(uint32_t*)&g_ctxh[base + nf * 8 + t2] = hi;
            *(uint32_t*)&g_ctxl[base + nf * 8 + t2] = lo;
        }
    }
}

// ---------------------------------------------------------------------------
// Output projection GEMM + bias (unchanged)
// ---------------------------------------------------------------------------
__global__ __launch_bounds__(256, 2) void proj_mma_kernel(
    const float* __restrict__ bias, float* __restrict__ out)
{
    const int m0 = blockIdx.y * 128, c0 = blockIdx.x * 128;
    float acc[4][4][4];
    gemm_bf16(g_ctxh, g_ctxl, g_wph, g_wpl, CH, m0, c0, acc);

    const int tid = threadIdx.x, lane = tid & 31, wid = tid >> 5;
    const int wm = (wid >> 2) * 64, wn = (wid & 3) * 32;
    const int g = lane >> 2, t2 = (lane & 3) * 2;

#pragma unroll
    for (int nf = 0; nf < 4; nf++) {
        const int col = c0 + wn + nf * 8 + t2;
        const float2 bv = *(const float2*)&bias[col];
#pragma unroll
        for (int mf = 0; mf < 4; mf++) {
#pragma unroll
            for (int rr = 0; rr < 2; rr++) {
                const int m = m0 + wm + mf * 16 + g + rr * 8;
                *(float2*)&out[(size_t)m * CH + col] =
                    make_float2(acc[mf][nf][rr * 2]     + bv.x,
                                acc[mf][nf][rr * 2 + 1] + bv.y);
            }
        }
    }
}

// ---------------------------------------------------------------------------
extern "C" void kernel_launch(void* const* d_in, const int* in_sizes, int n_in,
                              void* d_out, int out_size)
{
    const float* x      = (const float*)d_in[0];
    const float* w_qkv  = (const float*)d_in[1];
    const float* w_proj = (const float*)d_in[2];
    const float* b_proj = (const float*)d_in[3];
    float* out = (float*)d_out;

    const int gemm_smem  = 2 * STAGEGB;   // 81920
    const int flash_smem = 2 * STAGEFB;   // 73728
    cudaFuncSetAttribute(qkv_mma_kernel,
                         cudaFuncAttributeMaxDynamicSharedMemorySize, gemm_smem);
    cudaFuncSetAttribute(proj_mma_kernel,
                         cudaFuncAttributeMaxDynamicSharedMemorySize, gemm_smem);
    cudaFuncSetAttribute(flash_mma_kernel,
                         cudaFuncAttributeMaxDynamicSharedMemorySize, flash_smem);

    __nv_bfloat16 *p_xh, *p_xl, *p_wqh, *p_wql, *p_wph, *p_wpl;
    cudaGetSymbolAddress((void**)&p_xh,  g_xh);
    cudaGetSymbolAddress((void**)&p_xl,  g_xl);
    cudaGetSymbolAddress((void**)&p_wqh, g_wqh);
    cudaGetSymbolAddress((void**)&p_wql, g_wql);
    cudaGetSymbolAddress((void**)&p_wph, g_wph);
    cudaGetSymbolAddress((void**)&p_wpl, g_wpl);

    // pre-passes
    split_kernel<<<(MROWS*CH/4 + 255)/256, 256>>>(x, p_xh, p_xl, MROWS*CH/4);
    split_kernel<<<(QKVN*CH/4  + 255)/256, 256>>>(w_qkv, p_wqh, p_wql, QKVN*CH/4);
    split_kernel<<<(CH*CH/4    + 255)/256, 256>>>(w_proj, p_wph, p_wpl, CH*CH/4);
    rope_kernel<<<(SEQ*32 + 255)/256, 256>>>();

    dim3 g1(QKVN / 128, MROWS / 128);   // 18 x 32
    qkv_mma_kernel<<<g1, 256, gemm_smem>>>();

    dim3 g2(SEQ / 64, BB * NH);         // 32 x 24, 768 CTAs, 3/SM
    flash_mma_kernel<<<g2, 128, flash_smem>>>();

    dim3 g3(CH / 128, MROWS / 128);     // 6 x 32
    proj_mma_kernel<<<g3, 256, gemm_smem>>>(b_proj, out);
}

// round 13
// speedup vs baseline: 1.0074x; 1.0074x over previous
#include <cuda_runtime.h>
#include <cuda_bf16.h>
#include <math.h>
#include <stdint.h>

#define BB   2
#define SEQ  2048
#define CH   768
#define NH   12
#define HD   64
#define MROWS (BB*SEQ)      // 4096
#define QKVN  (3*CH)        // 2304
#define SSTR  40            // gemm smem stride (bf16)
#define KSTR  72            // flash smem stride (bf16)

// ---- device global scratch ----
__device__ __align__(16) __nv_bfloat16 g_xh[MROWS*CH],  g_xl[MROWS*CH];
__device__ __align__(16) __nv_bfloat16 g_wqh[QKVN*CH],  g_wql[QKVN*CH];
__device__ __align__(16) __nv_bfloat16 g_wph[CH*CH],    g_wpl[CH*CH];
__device__ __align__(16) __nv_bfloat16 g_qh[BB*NH*SEQ*HD], g_ql[BB*NH*SEQ*HD];
__device__ __align__(16) __nv_bfloat16 g_kh[BB*NH*SEQ*HD], g_kl[BB*NH*SEQ*HD];
__device__ __align__(16) __nv_bfloat16 g_vth[BB*NH*HD*SEQ], g_vtl[BB*NH*HD*SEQ];
__device__ __align__(16) __nv_bfloat16 g_ctxh[MROWS*CH], g_ctxl[MROWS*CH];
__device__ __align__(16) float2 g_rope[SEQ * 32];   // [n][dd/2] = (cos, sin)

// ===========================================================================
// helpers
// ===========================================================================
__device__ __forceinline__ uint32_t smem_to_u32(const void* p) {
    uint32_t a;
    asm("{ .reg .u64 t; cvta.to.shared.u64 t, %1; cvt.u32.u64 %0, t; }"
        : "=r"(a) : "l"(p));
    return a;
}
#define CP16(s, g) \
    asm volatile("cp.async.cg.shared.global [%0], [%1], 16;" :: "r"(s), "l"(g))
#define CP_COMMIT() asm volatile("cp.async.commit_group;" ::: "memory")
#define CP_WAIT1()  asm volatile("cp.async.wait_group 1;" ::: "memory")
#define CP_WAIT0()  asm volatile("cp.async.wait_group 0;" ::: "memory")

// NOTE: non-volatile — pure register dataflow, lets the compiler interleave
__device__ __forceinline__ void mma16816(float* c, const uint32_t* a,
                                         const uint32_t* b) {
    asm("mma.sync.aligned.m16n8k16.row.col.f32.bf16.bf16.f32 "
        "{%0,%1,%2,%3}, {%4,%5,%6,%7}, {%8,%9}, {%0,%1,%2,%3};"
        : "+f"(c[0]), "+f"(c[1]), "+f"(c[2]), "+f"(c[3])
        : "r"(a[0]), "r"(a[1]), "r"(a[2]), "r"(a[3]), "r"(b[0]), "r"(b[1]));
}
__device__ __forceinline__ void ldsm4(uint32_t r[4], uint32_t a) {
    asm volatile("ldmatrix.sync.aligned.m8n8.x4.shared.b16 {%0,%1,%2,%3}, [%4];"
        : "=r"(r[0]), "=r"(r[1]), "=r"(r[2]), "=r"(r[3]) : "r"(a));
}
__device__ __forceinline__ void splitpair(float x, float y,
                                          uint32_t& hi, uint32_t& lo) {
    __nv_bfloat16 hx = __float2bfloat16_rn(x), hy = __float2bfloat16_rn(y);
    __nv_bfloat162 h = __halves2bfloat162(hx, hy);
    hi = *(uint32_t*)&h;
    __nv_bfloat162 l = __floats2bfloat162_rn(x - __bfloat162float(hx),
                                             y - __bfloat162float(hy));
    lo = *(uint32_t*)&l;
}
// per-lane byte offsets for ldmatrix.x4 fragment loads
__device__ __forceinline__ uint32_t aoff_lane(int lane, int stride) {
    return (uint32_t)((((lane & 7) + ((lane >> 3) & 1) * 8) * stride +
                       ((lane >> 4) << 3)) * 2);
}
__device__ __forceinline__ uint32_t boff_lane(int lane, int stride) {
    return (uint32_t)((((lane & 7) + ((lane >> 4) << 3)) * stride +
                       ((lane >> 3) & 1) * 8) * 2);
}

// ---------------------------------------------------------------------------
// Pre-passes
// ---------------------------------------------------------------------------
__global__ void split_kernel(const float* __restrict__ src,
                             __nv_bfloat16* __restrict__ h,
                             __nv_bfloat16* __restrict__ l, int n4)
{
    int i = blockIdx.x * blockDim.x + threadIdx.x;
    if (i < n4) {
        float4 v = ((const float4*)src)[i];
        uint2 hi, lo;
        splitpair(v.x, v.y, hi.x, lo.x);
        splitpair(v.z, v.w, hi.y, lo.y);
        ((uint2*)h)[i] = hi;
        ((uint2*)l)[i] = lo;
    }
}
__global__ void rope_kernel()
{
    int i = blockIdx.x * blockDim.x + threadIdx.x;
    if (i < SEQ * 32) {
        int n = i >> 5, dd2 = i & 31;
        float freq = powf(10000.f, -((float)(2 * dd2)) / 64.f);
        float s, c;
        sincosf((float)n * freq, &s, &c);
        g_rope[i] = make_float2(c, s);
    }
}

// ---------------------------------------------------------------------------
// GEMM core: term-major MMA ordering (same-acc reuse distance 8)
// ---------------------------------------------------------------------------
#define ARRG  (128 * SSTR)
#define ARRGB (ARRG * 2)
#define STAGEGB (4 * ARRGB)

__device__ __forceinline__ void gemm_issue(
    uint32_t sb, const __nv_bfloat16* Ah, const __nv_bfloat16* Al,
    const __nv_bfloat16* Bh, const __nv_bfloat16* Bl,
    int K, int m0, int c0, int k0, int tid)
{
#pragma unroll
    for (int t = 0; t < 2; t++) {
        int f = tid + t * 256, r = f >> 2, c = (f & 3) * 8;
        uint32_t off = (uint32_t)(r * (SSTR * 2) + c * 2);
        CP16(sb + off,             &Ah[(size_t)(m0 + r) * K + k0 + c]);
        CP16(sb + ARRGB + off,     &Al[(size_t)(m0 + r) * K + k0 + c]);
        CP16(sb + 2 * ARRGB + off, &Bh[(size_t)(c0 + r) * K + k0 + c]);
        CP16(sb + 3 * ARRGB + off, &Bl[(size_t)(c0 + r) * K + k0 + c]);
    }
    CP_COMMIT();
}

__device__ __forceinline__ void gemm_bf16(
    const __nv_bfloat16* __restrict__ Ah, const __nv_bfloat16* __restrict__ Al,
    const __nv_bfloat16* __restrict__ Bh, const __nv_bfloat16* __restrict__ Bl,
    int K, int m0, int c0, float acc[4][4][4])
{
    extern __shared__ __nv_bfloat16 smp[];
    const uint32_t sb0 = smem_to_u32(smp);
    const int tid = threadIdx.x, lane = tid & 31, wid = tid >> 5;
    const int wm = (wid >> 2) * 64, wn = (wid & 3) * 32;
    const uint32_t ao = aoff_lane(lane, SSTR);
    const uint32_t bo = boff_lane(lane, SSTR);

#pragma unroll
    for (int i = 0; i < 4; i++)
#pragma unroll
        for (int j = 0; j < 4; j++)
#pragma unroll
            for (int r = 0; r < 4; r++) acc[i][j][r] = 0.f;

    const int nck = K / 32;
    gemm_issue(sb0, Ah, Al, Bh, Bl, K, m0, c0, 0, tid);

    for (int ck = 0; ck < nck; ck++) {
        if (ck + 1 < nck) {
            gemm_issue(sb0 + ((ck + 1) & 1) * STAGEGB, Ah, Al, Bh, Bl,
                       K, m0, c0, (ck + 1) * 32, tid);
            CP_WAIT1();
        } else {
            CP_WAIT0();
        }
        __syncthreads();

        const uint32_t st = sb0 + (ck & 1) * STAGEGB;
        const uint32_t cAh = st, cAl = st + ARRGB;
        const uint32_t cBh = st + 2 * ARRGB, cBl = st + 3 * ARRGB;

#pragma unroll
        for (int ks = 0; ks < 32; ks += 16) {
            uint32_t ah[4][4], al[4][4];
#pragma unroll
            for (int mf = 0; mf < 4; mf++) {
                uint32_t ra = (uint32_t)(((wm + mf * 16) * SSTR + ks) * 2) + ao;
                ldsm4(ah[mf], cAh + ra);
                ldsm4(al[mf], cAl + ra);
            }
#pragma unroll
            for (int p = 0; p < 2; p++) {
                uint32_t bh4[4], bl4[4];
                uint32_t rb = (uint32_t)(((wn + p * 16) * SSTR + ks) * 2) + bo;
                ldsm4(bh4, cBh + rb);
                ldsm4(bl4, cBl + rb);
                // term hh: 8 distinct accumulators
#pragma unroll
                for (int sub = 0; sub < 2; sub++)
#pragma unroll
                    for (int mf = 0; mf < 4; mf++)
                        mma16816(acc[mf][p * 2 + sub], ah[mf], &bh4[sub * 2]);
                // term hl
#pragma unroll
                for (int sub = 0; sub < 2; sub++)
#pragma unroll
                    for (int mf = 0; mf < 4; mf++)
                        mma16816(acc[mf][p * 2 + sub], ah[mf], &bl4[sub * 2]);
                // term lh
#pragma unroll
                for (int sub = 0; sub < 2; sub++)
#pragma unroll
                    for (int mf = 0; mf < 4; mf++)
                        mma16816(acc[mf][p * 2 + sub], al[mf], &bh4[sub * 2]);
            }
        }
        __syncthreads();
    }
}

// ---------------------------------------------------------------------------
// QKV GEMM + scale/RoPE(table) epilogue
// ---------------------------------------------------------------------------
__global__ __launch_bounds__(256, 2) void qkv_mma_kernel()
{
    const int m0 = blockIdx.y * 128, c0 = blockIdx.x * 128;
    float acc[4][4][4];
    gemm_bf16(g_xh, g_xl, g_wqh, g_wql, CH, m0, c0, acc);

    const int tid = threadIdx.x, lane = tid & 31, wid = tid >> 5;
    const int wm = (wid >> 2) * 64, wn = (wid & 3) * 32;
    const int g = lane >> 2, t2 = (lane & 3) * 2;

    const int which = (c0 + wn) / CH;
    const float sc = (which == 0) ? 0.125f : 1.0f;

#pragma unroll
    for (int nf = 0; nf < 4; nf++) {
        const int col = c0 + wn + nf * 8 + t2;
        const int h   = (col % CH) >> 6;
        const int dd  = col & 63;                 // even
#pragma unroll
        for (int mf = 0; mf < 4; mf++) {
#pragma unroll
            for (int rr = 0; rr < 2; rr++) {
                const int m = m0 + wm + mf * 16 + g + rr * 8;
                const int b = m >> 11, n = m & 2047;
                const int bh = b * NH + h;
                float x0 = acc[mf][nf][rr * 2], x1 = acc[mf][nf][rr * 2 + 1];
                if (which == 2) {
                    __nv_bfloat16 h0 = __float2bfloat16_rn(x0);
                    __nv_bfloat16 h1 = __float2bfloat16_rn(x1);
                    size_t o0 = ((size_t)bh * HD + dd) * SEQ + n;
                    g_vth[o0]       = h0;
                    g_vth[o0 + SEQ] = h1;
                    g_vtl[o0]       = __float2bfloat16_rn(x0 - __bfloat162float(h0));
                    g_vtl[o0 + SEQ] = __float2bfloat16_rn(x1 - __bfloat162float(h1));
                } else {
                    const float2 cs = g_rope[(n << 5) + (dd >> 1)];
                    x0 *= sc; x1 *= sc;
                    uint32_t hi, lo;
                    splitpair(x0 * cs.x - x1 * cs.y, x1 * cs.x + x0 * cs.y, hi, lo);
                    size_t o = ((size_t)bh * SEQ + n) * HD + dd;
                    if (which == 0) {
                        *(uint32_t*)&g_qh[o] = hi; *(uint32_t*)&g_ql[o] = lo;
                    } else {
                        *(uint32_t*)&g_kh[o] = hi; *(uint32_t*)&g_kl[o] = lo;
                    }
                }
            }
        }
    }
}

// ---------------------------------------------------------------------------
// Flash attention: 128 threads / 64 q-rows, 3 CTAs/SM, term-major MMA order
// ---------------------------------------------------------------------------
#define ARRF  (64 * KSTR)
#define ARRFB (ARRF * 2)
#define STAGEFB (4 * ARRFB)

__device__ __forceinline__ void flash_issue(uint32_t sb, int bh, int j0, int tid)
{
#pragma unroll
    for (int t = 0; t < 4; t++) {
        int f = tid + t * 128, r = f >> 3, c8 = (f & 7) * 8;
        uint32_t off = (uint32_t)(r * (KSTR * 2) + c8 * 2);
        CP16(sb + off,             &g_kh[((size_t)bh * SEQ + j0 + r) * HD + c8]);
        CP16(sb + ARRFB + off,     &g_kl[((size_t)bh * SEQ + j0 + r) * HD + c8]);
        CP16(sb + 2 * ARRFB + off, &g_vth[((size_t)bh * HD + r) * SEQ + j0 + c8]);
        CP16(sb + 3 * ARRFB + off, &g_vtl[((size_t)bh * HD + r) * SEQ + j0 + c8]);
    }
    CP_COMMIT();
}

__global__ __launch_bounds__(128, 3) void flash_mma_kernel()
{
    extern __shared__ __nv_bfloat16 fsm[];
    const uint32_t sb0 = smem_to_u32(fsm);

    const int tid = threadIdx.x, lane = tid & 31, wid = tid >> 5;  // wid 0..3
    const int g = lane >> 2, t2 = (lane & 3) * 2;
    const int bh = blockIdx.y;
    const int q0 = blockIdx.x * 64;
    const int qrow = q0 + wid * 16;
    const uint32_t bo = boff_lane(lane, KSTR);

    // Q fragments (hi/lo), register-resident
    uint32_t qa[2][4][4];
#pragma unroll
    for (int hl = 0; hl < 2; hl++) {
        const __nv_bfloat16* Qp = hl ? g_ql : g_qh;
        const size_t r0 = ((size_t)bh * SEQ + qrow + g) * HD;
        const size_t r1 = ((size_t)bh * SEQ + qrow + g + 8) * HD;
#pragma unroll
        for (int t = 0; t < 4; t++) {
            qa[hl][t][0] = *(const uint32_t*)&Qp[r0 + t * 16 + t2];
            qa[hl][t][1] = *(const uint32_t*)&Qp[r1 + t * 16 + t2];
            qa[hl][t][2] = *(const uint32_t*)&Qp[r0 + t * 16 + t2 + 8];
            qa[hl][t][3] = *(const uint32_t*)&Qp[r1 + t * 16 + t2 + 8];
        }
    }

    float o[8][4];
#pragma unroll
    for (int nf = 0; nf < 8; nf++)
#pragma unroll
        for (int r = 0; r < 4; r++) o[nf][r] = 0.f;
    float mi[2] = {-1e30f, -1e30f}, li[2] = {0.f, 0.f};

    flash_issue(sb0, bh, 0, tid);

    for (int jt = 0; jt < SEQ / 64; jt++) {
        if (jt + 1 < SEQ / 64) {
            flash_issue(sb0 + ((jt + 1) & 1) * STAGEFB, bh, (jt + 1) * 64, tid);
            CP_WAIT1();
        } else {
            CP_WAIT0();
        }
        __syncthreads();

        const uint32_t st = sb0 + (jt & 1) * STAGEFB;
        const uint32_t cKh = st, cKl = st + ARRFB;
        const uint32_t cVh = st + 2 * ARRFB, cVl = st + 3 * ARRFB;

        // S = Q.K^T (term-major over p-pairs: same-acc distance 4)
        float s[8][4];
#pragma unroll
        for (int nf = 0; nf < 8; nf++)
#pragma unroll
            for (int r = 0; r < 4; r++) s[nf][r] = 0.f;
#pragma unroll
        for (int t = 0; t < 4; t++) {
#pragma unroll
            for (int pp = 0; pp < 4; pp += 2) {
                uint32_t kh4[2][4], kl4[2][4];
#pragma unroll
                for (int q = 0; q < 2; q++) {
                    uint32_t rb = (uint32_t)(((pp + q) * 16 * KSTR + t * 16) * 2) + bo;
                    ldsm4(kh4[q], cKh + rb);
                    ldsm4(kl4[q], cKl + rb);
                }
                // term hh: 4 distinct accs
#pragma unroll
                for (int q = 0; q < 2; q++)
#pragma unroll
                    for (int sub = 0; sub < 2; sub++)
                        mma16816(s[(pp + q) * 2 + sub], qa[0][t], &kh4[q][sub * 2]);
                // term hl
#pragma unroll
                for (int q = 0; q < 2; q++)
#pragma unroll
                    for (int sub = 0; sub < 2; sub++)
                        mma16816(s[(pp + q) * 2 + sub], qa[0][t], &kl4[q][sub * 2]);
                // term lh
#pragma unroll
                for (int q = 0; q < 2; q++)
#pragma unroll
                    for (int sub = 0; sub < 2; sub++)
                        mma16816(s[(pp + q) * 2 + sub], qa[1][t], &kh4[q][sub * 2]);
            }
        }

        // online softmax (rows g, g+8)
#pragma unroll
        for (int rr = 0; rr < 2; rr++) {
            float mx = -1e30f;
#pragma unroll
            for (int nf = 0; nf < 8; nf++)
                mx = fmaxf(mx, fmaxf(s[nf][rr * 2], s[nf][rr * 2 + 1]));
            mx = fmaxf(mx, __shfl_xor_sync(0xffffffffu, mx, 1));
            mx = fmaxf(mx, __shfl_xor_sync(0xffffffffu, mx, 2));
            float mnew = fmaxf(mi[rr], mx);
            float alpha = __expf(mi[rr] - mnew);
            mi[rr] = mnew;
            float sum = 0.f;
#pragma unroll
            for (int nf = 0; nf < 8; nf++) {
                float p0 = __expf(s[nf][rr * 2]     - mnew);
                float p1 = __expf(s[nf][rr * 2 + 1] - mnew);
                s[nf][rr * 2] = p0; s[nf][rr * 2 + 1] = p1;
                sum += p0 + p1;
            }
            sum += __shfl_xor_sync(0xffffffffu, sum, 1);
            sum += __shfl_xor_sync(0xffffffffu, sum, 2);
            li[rr] = li[rr] * alpha + sum;
#pragma unroll
            for (int nf = 0; nf < 8; nf++) {
                o[nf][rr * 2] *= alpha; o[nf][rr * 2 + 1] *= alpha;
            }
        }

        // O += P.V (term-major over p-pairs)
#pragma unroll
        for (int t = 0; t < 4; t++) {
            uint32_t ph[4], pl[4];
            splitpair(s[2*t][0],   s[2*t][1],   ph[0], pl[0]);
            splitpair(s[2*t][2],   s[2*t][3],   ph[1], pl[1]);
            splitpair(s[2*t+1][0], s[2*t+1][1], ph[2], pl[2]);
            splitpair(s[2*t+1][2], s[2*t+1][3], ph[3], pl[3]);
#pragma unroll
            for (int pp = 0; pp < 4; pp += 2) {
                uint32_t vh4[2][4], vl4[2][4];
#pragma unroll
                for (int q = 0; q < 2; q++) {
                    uint32_t rb = (uint32_t)(((pp + q) * 16 * KSTR + t * 16) * 2) + bo;
                    ldsm4(vh4[q], cVh + rb);
                    ldsm4(vl4[q], cVl + rb);
                }
                // term hh
#pragma unroll
                for (int q = 0; q < 2; q++)
#pragma unroll
                    for (int sub = 0; sub < 2; sub++)
                        mma16816(o[(pp + q) * 2 + sub], ph, &vh4[q][sub * 2]);
                // term hl
#pragma unroll
                for (int q = 0; q < 2; q++)
#pragma unroll
                    for (int sub = 0; sub < 2; sub++)
                        mma16816(o[(pp + q) * 2 + sub], ph, &vl4[q][sub * 2]);
                // term lh
#pragma unroll
                for (int q = 0; q < 2; q++)
#pragma unroll
                    for (int sub = 0; sub < 2; sub++)
                        mma16816(o[(pp + q) * 2 + sub], pl, &vh4[q][sub * 2]);
            }
        }
        __syncthreads();
    }

    // epilogue: normalize, split, write ctx hi/lo bf16 [B][N][C]
    const int b = bh / NH, h = bh % NH;
    const float inv0 = 1.f / li[0], inv1 = 1.f / li[1];
#pragma unroll
    for (int rr = 0; rr < 2; rr++) {
        const int n = qrow + g + rr * 8;
        const float inv = rr ? inv1 : inv0;
        const size_t base = ((size_t)b * SEQ + n) * CH + h * HD;
#pragma unroll
        for (int nf = 0; nf < 8; nf++) {
            uint32_t hi, lo;
            splitpair(o[nf][rr * 2] * inv, o[nf][rr * 2 + 1] * inv, hi, lo);
            *(uint32_t*)&g_ctxh[base + nf * 8 + t2] = hi;
            *(uint32_t*)&g_ctxl[base + nf * 8 + t2] = lo;
        }
    }
}

// ---------------------------------------------------------------------------
// Output projection GEMM + bias
// ---------------------------------------------------------------------------
__global__ __launch_bounds__(256, 2) void proj_mma_kernel(
    const float* __restrict__ bias, float* __restrict__ out)
{
    const int m0 = blockIdx.y * 128, c0 = blockIdx.x * 128;
    float acc[4][4][4];
    gemm_bf16(g_ctxh, g_ctxl, g_wph, g_wpl, CH, m0, c0, acc);

    const int tid = threadIdx.x, lane = tid & 31, wid = tid >> 5;
    const int wm = (wid >> 2) * 64, wn = (wid & 3) * 32;
    const int g = lane >> 2, t2 = (lane & 3) * 2;

#pragma unroll
    for (int nf = 0; nf < 4; nf++) {
        const int col = c0 + wn + nf * 8 + t2;
        const float2 bv = *(const float2*)&bias[col];
#pragma unroll
        for (int mf = 0; mf < 4; mf++) {
#pragma unroll
            for (int rr = 0; rr < 2; rr++) {
                const int m = m0 + wm + mf * 16 + g + rr * 8;
                *(float2*)&out[(size_t)m * CH + col] =
                    make_float2(acc[mf][nf][rr * 2]     + bv.x,
                                acc[mf][nf][rr * 2 + 1] + bv.y);
            }
        }
    }
}

// ---------------------------------------------------------------------------
extern "C" void kernel_launch(void* const* d_in, const int* in_sizes, int n_in,
                              void* d_out, int out_size)
{
    const float* x      = (const float*)d_in[0];
    const float* w_qkv  = (const float*)d_in[1];
    const float* w_proj = (const float*)d_in[2];
    const float* b_proj = (const float*)d_in[3];
    float* out = (float*)d_out;

    const int gemm_smem  = 2 * STAGEGB;   // 81920
    const int flash_smem = 2 * STAGEFB;   // 73728
    cudaFuncSetAttribute(qkv_mma_kernel,
                         cudaFuncAttributeMaxDynamicSharedMemorySize, gemm_smem);
    cudaFuncSetAttribute(proj_mma_kernel,
                         cudaFuncAttributeMaxDynamicSharedMemorySize, gemm_smem);
    cudaFuncSetAttribute(flash_mma_kernel,
                         cudaFuncAttributeMaxDynamicSharedMemorySize, flash_smem);

    __nv_bfloat16 *p_xh, *p_xl, *p_wqh, *p_wql, *p_wph, *p_wpl;
    cudaGetSymbolAddress((void**)&p_xh,  g_xh);
    cudaGetSymbolAddress((void**)&p_xl,  g_xl);
    cudaGetSymbolAddress((void**)&p_wqh, g_wqh);
    cudaGetSymbolAddress((void**)&p_wql, g_wql);
    cudaGetSymbolAddress((void**)&p_wph, g_wph);
    cudaGetSymbolAddress((void**)&p_wpl, g_wpl);

    // pre-passes
    split_kernel<<<(MROWS*CH/4 + 255)/256, 256>>>(x, p_xh, p_xl, MROWS*CH/4);
    split_kernel<<<(QKVN*CH/4  + 255)/256, 256>>>(w_qkv, p_wqh, p_wql, QKVN*CH/4);
    split_kernel<<<(CH*CH/4    + 255)/256, 256>>>(w_proj, p_wph, p_wpl, CH*CH/4);
    rope_kernel<<<(SEQ*32 + 255)/256, 256>>>();

    dim3 g1(QKVN / 128, MROWS / 128);   // 18 x 32
    qkv_mma_kernel<<<g1, 256, gemm_smem>>>();

    dim3 g2(SEQ / 64, BB * NH);         // 32 x 24, 768 CTAs, 3/SM
    flash_mma_kernel<<<g2, 128, flash_smem>>>();

    dim3 g3(CH / 128, MROWS / 128);     // 6 x 32
    proj_mma_kernel<<<g3, 256, gemm_smem>>>(b_proj, out);
}

// round 14
// speedup vs baseline: 1.0864x; 1.0784x over previous
#include <cuda_runtime.h>
#include <cuda_bf16.h>
#include <math.h>
#include <stdint.h>

#define BB   2
#define SEQ  2048
#define CH   768
#define NH   12
#define HD   64
#define MROWS (BB*SEQ)      // 4096
#define QKVN  (3*CH)        // 2304

// ---- device global scratch ----
__device__ __align__(16) __nv_bfloat16 g_xh[MROWS*CH],  g_xl[MROWS*CH];
__device__ __align__(16) __nv_bfloat16 g_wqh[QKVN*CH],  g_wql[QKVN*CH];
__device__ __align__(16) __nv_bfloat16 g_wph[CH*CH],    g_wpl[CH*CH];
__device__ __align__(16) __nv_bfloat16 g_qh[BB*NH*SEQ*HD], g_ql[BB*NH*SEQ*HD];
__device__ __align__(16) __nv_bfloat16 g_kh[BB*NH*SEQ*HD], g_kl[BB*NH*SEQ*HD];
__device__ __align__(16) __nv_bfloat16 g_vth[BB*NH*HD*SEQ], g_vtl[BB*NH*HD*SEQ];
__device__ __align__(16) __nv_bfloat16 g_ctxh[MROWS*CH], g_ctxl[MROWS*CH];
__device__ __align__(16) float2 g_rope[SEQ * 32];   // [n][dd/2] = (cos, sin)

// ===========================================================================
// helpers
// ===========================================================================
__device__ __forceinline__ uint32_t smem_to_u32(const void* p) {
    uint32_t a;
    asm("{ .reg .u64 t; cvta.to.shared.u64 t, %1; cvt.u32.u64 %0, t; }"
        : "=r"(a) : "l"(p));
    return a;
}
#define CP16(s, g) \
    asm volatile("cp.async.cg.shared.global [%0], [%1], 16;" :: "r"(s), "l"(g))
#define CP_COMMIT() asm volatile("cp.async.commit_group;" ::: "memory")
#define CP_WAIT1()  asm volatile("cp.async.wait_group 1;" ::: "memory")
#define CP_WAIT0()  asm volatile("cp.async.wait_group 0;" ::: "memory")

__device__ __forceinline__ void mma16816(float* c, const uint32_t* a,
                                         const uint32_t* b) {
    asm("mma.sync.aligned.m16n8k16.row.col.f32.bf16.bf16.f32 "
        "{%0,%1,%2,%3}, {%4,%5,%6,%7}, {%8,%9}, {%0,%1,%2,%3};"
        : "+f"(c[0]), "+f"(c[1]), "+f"(c[2]), "+f"(c[3])
        : "r"(a[0]), "r"(a[1]), "r"(a[2]), "r"(a[3]), "r"(b[0]), "r"(b[1]));
}
__device__ __forceinline__ void ldsm4(uint32_t r[4], uint32_t a) {
    asm volatile("ldmatrix.sync.aligned.m8n8.x4.shared.b16 {%0,%1,%2,%3}, [%4];"
        : "=r"(r[0]), "=r"(r[1]), "=r"(r[2]), "=r"(r[3]) : "r"(a));
}
__device__ __forceinline__ void splitpair(float x, float y,
                                          uint32_t& hi, uint32_t& lo) {
    __nv_bfloat16 hx = __float2bfloat16_rn(x), hy = __float2bfloat16_rn(y);
    __nv_bfloat162 h = __halves2bfloat162(hx, hy);
    hi = *(uint32_t*)&h;
    __nv_bfloat162 l = __floats2bfloat162_rn(x - __bfloat162float(hx),
                                             y - __bfloat162float(hy));
    lo = *(uint32_t*)&l;
}

// ---------------------------------------------------------------------------
// Pre-passes
// ---------------------------------------------------------------------------
__global__ void split_kernel(const float* __restrict__ src,
                             __nv_bfloat16* __restrict__ h,
                             __nv_bfloat16* __restrict__ l, int n4)
{
    int i = blockIdx.x * blockDim.x + threadIdx.x;
    if (i < n4) {
        float4 v = ((const float4*)src)[i];
        uint2 hi, lo;
        splitpair(v.x, v.y, hi.x, lo.x);
        splitpair(v.z, v.w, hi.y, lo.y);
        ((uint2*)h)[i] = hi;
        ((uint2*)l)[i] = lo;
    }
}
__global__ void rope_kernel()
{
    int i = blockIdx.x * blockDim.x + threadIdx.x;
    if (i < SEQ * 32) {
        int n = i >> 5, dd2 = i & 31;
        float freq = powf(10000.f, -((float)(2 * dd2)) / 64.f);
        float s, c;
        sincosf((float)n * freq, &s, &c);
        g_rope[i] = make_float2(c, s);
    }
}

// ===========================================================================
// GEMM core: 3-stage cp.async pipeline, 1 sync/chunk, XOR-swizzled 128B rows.
// Stage (32KB): A-array 16KB [128 rows x 128B: hi 64B | lo 64B], B-array same.
// ===========================================================================
#define STG_G 32768

__device__ __forceinline__ void gemm_issue(
    uint32_t sb, const __nv_bfloat16* Ah, const __nv_bfloat16* Al,
    const __nv_bfloat16* Bh, const __nv_bfloat16* Bl,
    int K, int m0, int c0, int k0, int tid)
{
#pragma unroll
    for (int t = 0; t < 4; t++) {
        int f = tid + t * 256;        // 0..1023
        int r = f >> 3, c = f & 7;
        int col = (c & 3) * 8;
        uint32_t dst = sb + (uint32_t)(r * 128 + ((c ^ (r & 7)) << 4));
        const __nv_bfloat16* sa = (c < 4) ? &Ah[(size_t)(m0 + r) * K + k0 + col]
                                          : &Al[(size_t)(m0 + r) * K + k0 + col];
        CP16(dst, sa);
        const __nv_bfloat16* sb2 = (c < 4) ? &Bh[(size_t)(c0 + r) * K + k0 + col]
                                           : &Bl[(size_t)(c0 + r) * K + k0 + col];
        CP16(dst + 16384, sb2);
    }
    CP_COMMIT();
}

__device__ __forceinline__ void gemm_bf16(
    const __nv_bfloat16* __restrict__ Ah, const __nv_bfloat16* __restrict__ Al,
    const __nv_bfloat16* __restrict__ Bh, const __nv_bfloat16* __restrict__ Bl,
    int K, int m0, int c0, float acc[4][4][4])
{
    extern __shared__ __nv_bfloat16 smp[];
    const uint32_t sb0 = smem_to_u32(smp);
    const int tid = threadIdx.x, lane = tid & 31, wid = tid >> 5;
    const int wm = (wid >> 2) * 64, wn = (wid & 3) * 32;
    const int x7 = lane & 7;
    const int arow = (lane & 7) + ((lane >> 3) & 1) * 8;   // A-frag row-in-tile
    const int ak   = lane >> 4;                             // A-frag chunk add
    const int brow = (lane & 7) + ((lane >> 4) << 3);       // B-frag row-in-tile
    const int bk   = (lane >> 3) & 1;                       // B-frag chunk add

#pragma unroll
    for (int i = 0; i < 4; i++)
#pragma unroll
        for (int j = 0; j < 4; j++)
#pragma unroll
            for (int r = 0; r < 4; r++) acc[i][j][r] = 0.f;

    const int nck = K / 32;   // 24
    gemm_issue(sb0,          Ah, Al, Bh, Bl, K, m0, c0, 0,  tid);
    gemm_issue(sb0 + STG_G,  Ah, Al, Bh, Bl, K, m0, c0, 32, tid);

    for (int ck = 0; ck < nck; ck++) {
        if (ck + 1 < nck) CP_WAIT1(); else CP_WAIT0();
        __syncthreads();
        if (ck + 2 < nck)
            gemm_issue(sb0 + ((ck + 2) % 3) * STG_G, Ah, Al, Bh, Bl,
                       K, m0, c0, (ck + 2) * 32, tid);

        const uint32_t stA = sb0 + (ck % 3) * STG_G;
        const uint32_t stB = stA + 16384;

#pragma unroll
        for (int ks = 0; ks < 32; ks += 16) {
            const int kc = ks >> 3;     // chunk base 0 or 2
            uint32_t ah[4][4], al[4][4];
#pragma unroll
            for (int mf = 0; mf < 4; mf++) {
                uint32_t ra = stA + (uint32_t)((wm + mf * 16 + arow) * 128 +
                                   (((kc + ak) ^ x7) << 4));
                ldsm4(ah[mf], ra);
                ldsm4(al[mf], ra ^ 64u);     // lo half: chunk+4
            }
#pragma unroll
            for (int p = 0; p < 2; p++) {
                uint32_t bh4[4], bl4[4];
                uint32_t rb = stB + (uint32_t)((wn + p * 16 + brow) * 128 +
                                   (((kc + bk) ^ x7) << 4));
                ldsm4(bh4, rb);
                ldsm4(bl4, rb ^ 64u);
#pragma unroll
                for (int sub = 0; sub < 2; sub++)
#pragma unroll
                    for (int mf = 0; mf < 4; mf++)
                        mma16816(acc[mf][p * 2 + sub], ah[mf], &bh4[sub * 2]);
#pragma unroll
                for (int sub = 0; sub < 2; sub++)
#pragma unroll
                    for (int mf = 0; mf < 4; mf++)
                        mma16816(acc[mf][p * 2 + sub], ah[mf], &bl4[sub * 2]);
#pragma unroll
                for (int sub = 0; sub < 2; sub++)
#pragma unroll
                    for (int mf = 0; mf < 4; mf++)
                        mma16816(acc[mf][p * 2 + sub], al[mf], &bh4[sub * 2]);
            }
        }
    }
}

// ---------------------------------------------------------------------------
// QKV GEMM + scale/RoPE(table) epilogue
// ---------------------------------------------------------------------------
__global__ __launch_bounds__(256, 2) void qkv_mma_kernel()
{
    const int m0 = blockIdx.y * 128, c0 = blockIdx.x * 128;
    float acc[4][4][4];
    gemm_bf16(g_xh, g_xl, g_wqh, g_wql, CH, m0, c0, acc);

    const int tid = threadIdx.x, lane = tid & 31, wid = tid >> 5;
    const int wm = (wid >> 2) * 64, wn = (wid & 3) * 32;
    const int g = lane >> 2, t2 = (lane & 3) * 2;

    const int which = (c0 + wn) / CH;
    const float sc = (which == 0) ? 0.125f : 1.0f;

#pragma unroll
    for (int nf = 0; nf < 4; nf++) {
        const int col = c0 + wn + nf * 8 + t2;
        const int h   = (col % CH) >> 6;
        const int dd  = col & 63;                 // even
#pragma unroll
        for (int mf = 0; mf < 4; mf++) {
#pragma unroll
            for (int rr = 0; rr < 2; rr++) {
                const int m = m0 + wm + mf * 16 + g + rr * 8;
                const int b = m >> 11, n = m & 2047;
                const int bh = b * NH + h;
                float x0 = acc[mf][nf][rr * 2], x1 = acc[mf][nf][rr * 2 + 1];
                if (which == 2) {
                    __nv_bfloat16 h0 = __float2bfloat16_rn(x0);
                    __nv_bfloat16 h1 = __float2bfloat16_rn(x1);
                    size_t o0 = ((size_t)bh * HD + dd) * SEQ + n;
                    g_vth[o0]       = h0;
                    g_vth[o0 + SEQ] = h1;
                    g_vtl[o0]       = __float2bfloat16_rn(x0 - __bfloat162float(h0));
                    g_vtl[o0 + SEQ] = __float2bfloat16_rn(x1 - __bfloat162float(h1));
                } else {
                    const float2 cs = g_rope[(n << 5) + (dd >> 1)];
                    x0 *= sc; x1 *= sc;
                    uint32_t hi, lo;
                    splitpair(x0 * cs.x - x1 * cs.y, x1 * cs.x + x0 * cs.y, hi, lo);
                    size_t o = ((size_t)bh * SEQ + n) * HD + dd;
                    if (which == 0) {
                        *(uint32_t*)&g_qh[o] = hi; *(uint32_t*)&g_ql[o] = lo;
                    } else {
                        *(uint32_t*)&g_kh[o] = hi; *(uint32_t*)&g_kl[o] = lo;
                    }
                }
            }
        }
    }
}

// ===========================================================================
// Flash attention: 256 threads / 128 q-rows, 3-stage pipeline, 1 sync/tile,
// XOR-swizzled 128B rows. Stage (32KB): Kh|Kl|Vh|Vl arrays of 8KB each.
// ===========================================================================
#define STG_F 32768

__device__ __forceinline__ void flash_issue(uint32_t sb, int bh, int j0, int tid)
{
#pragma unroll
    for (int t = 0; t < 2; t++) {
        int f = tid + t * 256;      // 0..511
        int r = f >> 3, c = f & 7;
        int col = c * 8;
        uint32_t off = (uint32_t)(r * 128 + ((c ^ (r & 7)) << 4));
        CP16(sb + off,         &g_kh[((size_t)bh * SEQ + j0 + r) * HD + col]);
        CP16(sb + 8192 + off,  &g_kl[((size_t)bh * SEQ + j0 + r) * HD + col]);
        CP16(sb + 16384 + off, &g_vth[((size_t)bh * HD + r) * SEQ + j0 + col]);
        CP16(sb + 24576 + off, &g_vtl[((size_t)bh * HD + r) * SEQ + j0 + col]);
    }
    CP_COMMIT();
}

__global__ __launch_bounds__(256, 2) void flash_mma_kernel()
{
    extern __shared__ __nv_bfloat16 fsm[];
    const uint32_t sb0 = smem_to_u32(fsm);

    const int tid = threadIdx.x, lane = tid & 31, wid = tid >> 5;  // wid 0..7
    const int g = lane >> 2, t2 = (lane & 3) * 2;
    const int bh = blockIdx.y;
    const int q0 = blockIdx.x * 128;
    const int qrow = q0 + wid * 16;
    const int x7 = lane & 7;
    const int brow = (lane & 7) + ((lane >> 4) << 3);
    const int bk   = (lane >> 3) & 1;

    // Q fragments (hi/lo), register-resident
    uint32_t qa[2][4][4];
#pragma unroll
    for (int hl = 0; hl < 2; hl++) {
        const __nv_bfloat16* Qp = hl ? g_ql : g_qh;
        const size_t r0 = ((size_t)bh * SEQ + qrow + g) * HD;
        const size_t r1 = ((size_t)bh * SEQ + qrow + g + 8) * HD;
#pragma unroll
        for (int t = 0; t < 4; t++) {
            qa[hl][t][0] = *(const uint32_t*)&Qp[r0 + t * 16 + t2];
            qa[hl][t][1] = *(const uint32_t*)&Qp[r1 + t * 16 + t2];
            qa[hl][t][2] = *(const uint32_t*)&Qp[r0 + t * 16 + t2 + 8];
            qa[hl][t][3] = *(const uint32_t*)&Qp[r1 + t * 16 + t2 + 8];
        }
    }

    float o[8][4];
#pragma unroll
    for (int nf = 0; nf < 8; nf++)
#pragma unroll
        for (int r = 0; r < 4; r++) o[nf][r] = 0.f;
    float mi[2] = {-1e30f, -1e30f}, li[2] = {0.f, 0.f};

    const int ntile = SEQ / 64;   // 32
    flash_issue(sb0,         bh, 0,  tid);
    flash_issue(sb0 + STG_F, bh, 64, tid);

    for (int jt = 0; jt < ntile; jt++) {
        if (jt + 1 < ntile) CP_WAIT1(); else CP_WAIT0();
        __syncthreads();
        if (jt + 2 < ntile)
            flash_issue(sb0 + ((jt + 2) % 3) * STG_F, bh, (jt + 2) * 64, tid);

        const uint32_t st = sb0 + (jt % 3) * STG_F;
        const uint32_t cKh = st, cKl = st + 8192;
        const uint32_t cVh = st + 16384, cVl = st + 24576;

        // S = Q.K^T
        float s[8][4];
#pragma unroll
        for (int nf = 0; nf < 8; nf++)
#pragma unroll
            for (int r = 0; r < 4; r++) s[nf][r] = 0.f;
#pragma unroll
        for (int t = 0; t < 4; t++) {
#pragma unroll
            for (int p = 0; p < 4; p++) {
                uint32_t kh4[4], kl4[4];
                uint32_t rb = (uint32_t)((p * 16 + brow) * 128 +
                                         (((2 * t + bk) ^ x7) << 4));
                ldsm4(kh4, cKh + rb);
                ldsm4(kl4, cKl + rb);
#pragma unroll
                for (int sub = 0; sub < 2; sub++) {
                    const int nf = p * 2 + sub;
                    mma16816(s[nf], qa[0][t], &kh4[sub * 2]);
                    mma16816(s[nf], qa[0][t], &kl4[sub * 2]);
                    mma16816(s[nf], qa[1][t], &kh4[sub * 2]);
                }
            }
        }

        // online softmax (rows g, g+8)
#pragma unroll
        for (int rr = 0; rr < 2; rr++) {
            float mx = -1e30f;
#pragma unroll
            for (int nf = 0; nf < 8; nf++)
                mx = fmaxf(mx, fmaxf(s[nf][rr * 2], s[nf][rr * 2 + 1]));
            mx = fmaxf(mx, __shfl_xor_sync(0xffffffffu, mx, 1));
            mx = fmaxf(mx, __shfl_xor_sync(0xffffffffu, mx, 2));
            float mnew = fmaxf(mi[rr], mx);
            float alpha = __expf(mi[rr] - mnew);
            mi[rr] = mnew;
            float sum = 0.f;
#pragma unroll
            for (int nf = 0; nf < 8; nf++) {
                float p0 = __expf(s[nf][rr * 2]     - mnew);
                float p1 = __expf(s[nf][rr * 2 + 1] - mnew);
                s[nf][rr * 2] = p0; s[nf][rr * 2 + 1] = p1;
                sum += p0 + p1;
            }
            sum += __shfl_xor_sync(0xffffffffu, sum, 1);
            sum += __shfl_xor_sync(0xffffffffu, sum, 2);
            li[rr] = li[rr] * alpha + sum;
#pragma unroll
            for (int nf = 0; nf < 8; nf++) {
                o[nf][rr * 2] *= alpha; o[nf][rr * 2 + 1] *= alpha;
            }
        }

        // O += P.V
#pragma unroll
        for (int t = 0; t < 4; t++) {
            uint32_t ph[4], pl[4];
            splitpair(s[2*t][0],   s[2*t][1],   ph[0], pl[0]);
            splitpair(s[2*t][2],   s[2*t][3],   ph[1], pl[1]);
            splitpair(s[2*t+1][0], s[2*t+1][1], ph[2], pl[2]);
            splitpair(s[2*t+1][2], s[2*t+1][3], ph[3], pl[3]);
#pragma unroll
            for (int p = 0; p < 4; p++) {
                uint32_t vh4[4], vl4[4];
                uint32_t rb = (uint32_t)((p * 16 + brow) * 128 +
                                         (((2 * t + bk) ^ x7) << 4));
                ldsm4(vh4, cVh + rb);
                ldsm4(vl4, cVl + rb);
#pragma unroll
                for (int sub = 0; sub < 2; sub++) {
                    const int nf = p * 2 + sub;
                    mma16816(o[nf], ph, &vh4[sub * 2]);
                    mma16816(o[nf], ph, &vl4[sub * 2]);
                    mma16816(o[nf], pl, &vh4[sub * 2]);
                }
            }
        }
    }

    // epilogue: normalize, split, write ctx hi/lo bf16 [B][N][C]
    const int b = bh / NH, h = bh % NH;
    const float inv0 = 1.f / li[0], inv1 = 1.f / li[1];
#pragma unroll
    for (int rr = 0; rr < 2; rr++) {
        const int n = qrow + g + rr * 8;
        const float inv = rr ? inv1 : inv0;
        const size_t base = ((size_t)b * SEQ + n) * CH + h * HD;
#pragma unroll
        for (int nf = 0; nf < 8; nf++) {
            uint32_t hi, lo;
            splitpair(o[nf][rr * 2] * inv, o[nf][rr * 2 + 1] * inv, hi, lo);
            *(uint32_t*)&g_ctxh[base + nf * 8 + t2] = hi;
            *(uint32_t*)&g_ctxl[base + nf * 8 + t2] = lo;
        }
    }
}

// ---------------------------------------------------------------------------
// Output projection GEMM + bias
// ---------------------------------------------------------------------------
__global__ __launch_bounds__(256, 2) void proj_mma_kernel(
    const float* __restrict__ bias, float* __restrict__ out)
{
    const int m0 = blockIdx.y * 128, c0 = blockIdx.x * 128;
    float acc[4][4][4];
    gemm_bf16(g_ctxh, g_ctxl, g_wph, g_wpl, CH, m0, c0, acc);

    const int tid = threadIdx.x, lane = tid & 31, wid = tid >> 5;
    const int wm = (wid >> 2) * 64, wn = (wid & 3) * 32;
    const int g = lane >> 2, t2 = (lane & 3) * 2;

#pragma unroll
    for (int nf = 0; nf < 4; nf++) {
        const int col = c0 + wn + nf * 8 + t2;
        const float2 bv = *(const float2*)&bias[col];
#pragma unroll
        for (int mf = 0; mf < 4; mf++) {
#pragma unroll
            for (int rr = 0; rr < 2; rr++) {
                const int m = m0 + wm + mf * 16 + g + rr * 8;
                *(float2*)&out[(size_t)m * CH + col] =
                    make_float2(acc[mf][nf][rr * 2]     + bv.x,
                                acc[mf][nf][rr * 2 + 1] + bv.y);
            }
        }
    }
}

// ---------------------------------------------------------------------------
extern "C" void kernel_launch(void* const* d_in, const int* in_sizes, int n_in,
                              void* d_out, int out_size)
{
    const float* x      = (const float*)d_in[0];
    const float* w_qkv  = (const float*)d_in[1];
    const float* w_proj = (const float*)d_in[2];
    const float* b_proj = (const float*)d_in[3];
    float* out = (float*)d_out;

    const int gemm_smem  = 3 * STG_G;   // 98304
    const int flash_smem = 3 * STG_F;   // 98304
    cudaFuncSetAttribute(qkv_mma_kernel,
                         cudaFuncAttributeMaxDynamicSharedMemorySize, gemm_smem);
    cudaFuncSetAttribute(proj_mma_kernel,
                         cudaFuncAttributeMaxDynamicSharedMemorySize, gemm_smem);
    cudaFuncSetAttribute(flash_mma_kernel,
                         cudaFuncAttributeMaxDynamicSharedMemorySize, flash_smem);

    __nv_bfloat16 *p_xh, *p_xl, *p_wqh, *p_wql, *p_wph, *p_wpl;
    cudaGetSymbolAddress((void**)&p_xh,  g_xh);
    cudaGetSymbolAddress((void**)&p_xl,  g_xl);
    cudaGetSymbolAddress((void**)&p_wqh, g_wqh);
    cudaGetSymbolAddress((void**)&p_wql, g_wql);
    cudaGetSymbolAddress((void**)&p_wph, g_wph);
    cudaGetSymbolAddress((void**)&p_wpl, g_wpl);

    // pre-passes
    split_kernel<<<(MROWS*CH/4 + 255)/256, 256>>>(x, p_xh, p_xl, MROWS*CH/4);
    split_kernel<<<(QKVN*CH/4  + 255)/256, 256>>>(w_qkv, p_wqh, p_wql, QKVN*CH/4);
    split_kernel<<<(CH*CH/4    + 255)/256, 256>>>(w_proj, p_wph, p_wpl, CH*CH/4);
    rope_kernel<<<(SEQ*32 + 255)/256, 256>>>();

    dim3 g1(QKVN / 128, MROWS / 128);   // 18 x 32
    qkv_mma_kernel<<<g1, 256, gemm_smem>>>();

    dim3 g2(SEQ / 128, BB * NH);        // 16 x 24
    flash_mma_kernel<<<g2, 256, flash_smem>>>();

    dim3 g3(CH / 128, MROWS / 128);     // 6 x 32
    proj_mma_kernel<<<g3, 256, gemm_smem>>>(b_proj, out);
}

// round 15
// speedup vs baseline: 1.2706x; 1.1695x over previous
#include <cuda_runtime.h>
#include <cuda_bf16.h>
#include <cuda_fp16.h>
#include <math.h>
#include <stdint.h>

#define BB   2
#define SEQ  2048
#define CH   768
#define NH   12
#define HD   64
#define MROWS (BB*SEQ)      // 4096
#define QKVN  (3*CH)        // 2304

// ---- device global scratch ----
__device__ __align__(16) __nv_bfloat16 g_xh[MROWS*CH],  g_xl[MROWS*CH];
__device__ __align__(16) __nv_bfloat16 g_wqh[QKVN*CH],  g_wql[QKVN*CH];
__device__ __align__(16) __half        g_wph[CH*CH],    g_wpl[CH*CH];
__device__ __align__(16) __nv_bfloat16 g_qh[BB*NH*SEQ*HD], g_ql[BB*NH*SEQ*HD];
__device__ __align__(16) __nv_bfloat16 g_kh[BB*NH*SEQ*HD], g_kl[BB*NH*SEQ*HD];
__device__ __align__(16) __half        g_vth[BB*NH*HD*SEQ], g_vtl[BB*NH*HD*SEQ];
__device__ __align__(16) __half        g_ctxf[MROWS*CH];
__device__ __align__(16) float2 g_rope[SEQ * 32];   // [n][dd/2] = (cos, sin)

// ===========================================================================
// helpers
// ===========================================================================
__device__ __forceinline__ uint32_t smem_to_u32(const void* p) {
    uint32_t a;
    asm("{ .reg .u64 t; cvta.to.shared.u64 t, %1; cvt.u32.u64 %0, t; }"
        : "=r"(a) : "l"(p));
    return a;
}
#define CP16(s, g) \
    asm volatile("cp.async.cg.shared.global [%0], [%1], 16;" :: "r"(s), "l"(g))
#define CP_COMMIT() asm volatile("cp.async.commit_group;" ::: "memory")
#define CP_WAIT1()  asm volatile("cp.async.wait_group 1;" ::: "memory")
#define CP_WAIT0()  asm volatile("cp.async.wait_group 0;" ::: "memory")

__device__ __forceinline__ void mma16816(float* c, const uint32_t* a,
                                         const uint32_t* b) {
    asm("mma.sync.aligned.m16n8k16.row.col.f32.bf16.bf16.f32 "
        "{%0,%1,%2,%3}, {%4,%5,%6,%7}, {%8,%9}, {%0,%1,%2,%3};"
        : "+f"(c[0]), "+f"(c[1]), "+f"(c[2]), "+f"(c[3])
        : "r"(a[0]), "r"(a[1]), "r"(a[2]), "r"(a[3]), "r"(b[0]), "r"(b[1]));
}
__device__ __forceinline__ void mma16816h(float* c, const uint32_t* a,
                                          const uint32_t* b) {
    asm("mma.sync.aligned.m16n8k16.row.col.f32.f16.f16.f32 "
        "{%0,%1,%2,%3}, {%4,%5,%6,%7}, {%8,%9}, {%0,%1,%2,%3};"
        : "+f"(c[0]), "+f"(c[1]), "+f"(c[2]), "+f"(c[3])
        : "r"(a[0]), "r"(a[1]), "r"(a[2]), "r"(a[3]), "r"(b[0]), "r"(b[1]));
}
__device__ __forceinline__ void ldsm4(uint32_t r[4], uint32_t a) {
    asm volatile("ldmatrix.sync.aligned.m8n8.x4.shared.b16 {%0,%1,%2,%3}, [%4];"
        : "=r"(r[0]), "=r"(r[1]), "=r"(r[2]), "=r"(r[3]) : "r"(a));
}
__device__ __forceinline__ void splitpair(float x, float y,
                                          uint32_t& hi, uint32_t& lo) {
    __nv_bfloat16 hx = __float2bfloat16_rn(x), hy = __float2bfloat16_rn(y);
    __nv_bfloat162 h = __halves2bfloat162(hx, hy);
    hi = *(uint32_t*)&h;
    __nv_bfloat162 l = __floats2bfloat162_rn(x - __bfloat162float(hx),
                                             y - __bfloat162float(hy));
    lo = *(uint32_t*)&l;
}
__device__ __forceinline__ uint32_t pack_h2(float x, float y) {
    __half2 h = __floats2half2_rn(x, y);
    return *(uint32_t*)&h;
}

// ---------------------------------------------------------------------------
// Pre-passes
// ---------------------------------------------------------------------------
__global__ void split_kernel(const float* __restrict__ src,
                             __nv_bfloat16* __restrict__ h,
                             __nv_bfloat16* __restrict__ l, int n4)
{
    int i = blockIdx.x * blockDim.x + threadIdx.x;
    if (i < n4) {
        float4 v = ((const float4*)src)[i];
        uint2 hi, lo;
        splitpair(v.x, v.y, hi.x, lo.x);
        splitpair(v.z, v.w, hi.y, lo.y);
        ((uint2*)h)[i] = hi;
        ((uint2*)l)[i] = lo;
    }
}
__global__ void split_kernel_f16(const float* __restrict__ src,
                                 __half* __restrict__ h,
                                 __half* __restrict__ l, int n4)
{
    int i = blockIdx.x * blockDim.x + threadIdx.x;
    if (i < n4) {
        float4 v = ((const float4*)src)[i];
        __half hx = __float2half_rn(v.x), hy = __float2half_rn(v.y),
               hz = __float2half_rn(v.z), hw = __float2half_rn(v.w);
        uint2 hi, lo;
        hi.x = pack_h2(v.x, v.y); hi.y = pack_h2(v.z, v.w);
        lo.x = pack_h2(v.x - __half2float(hx), v.y - __half2float(hy));
        lo.y = pack_h2(v.z - __half2float(hz), v.w - __half2float(hw));
        ((uint2*)h)[i] = hi;
        ((uint2*)l)[i] = lo;
    }
}
__global__ void rope_kernel()
{
    int i = blockIdx.x * blockDim.x + threadIdx.x;
    if (i < SEQ * 32) {
        int n = i >> 5, dd2 = i & 31;
        float freq = powf(10000.f, -((float)(2 * dd2)) / 64.f);
        float s, c;
        sincosf((float)n * freq, &s, &c);
        g_rope[i] = make_float2(c, s);
    }
}

// ===========================================================================
// bf16 3-term GEMM core (qkv): 3-stage cp.async, XOR-swizzled 128B rows.
// ===========================================================================
#define STG_G 32768

__device__ __forceinline__ void gemm_issue(
    uint32_t sb, const __nv_bfloat16* Ah, const __nv_bfloat16* Al,
    const __nv_bfloat16* Bh, const __nv_bfloat16* Bl,
    int K, int m0, int c0, int k0, int tid)
{
#pragma unroll
    for (int t = 0; t < 4; t++) {
        int f = tid + t * 256;
        int r = f >> 3, c = f & 7;
        int col = (c & 3) * 8;
        uint32_t dst = sb + (uint32_t)(r * 128 + ((c ^ (r & 7)) << 4));
        const __nv_bfloat16* sa = (c < 4) ? &Ah[(size_t)(m0 + r) * K + k0 + col]
                                          : &Al[(size_t)(m0 + r) * K + k0 + col];
        CP16(dst, sa);
        const __nv_bfloat16* sb2 = (c < 4) ? &Bh[(size_t)(c0 + r) * K + k0 + col]
                                           : &Bl[(size_t)(c0 + r) * K + k0 + col];
        CP16(dst + 16384, sb2);
    }
    CP_COMMIT();
}

__device__ __forceinline__ void gemm_bf16(
    const __nv_bfloat16* __restrict__ Ah, const __nv_bfloat16* __restrict__ Al,
    const __nv_bfloat16* __restrict__ Bh, const __nv_bfloat16* __restrict__ Bl,
    int K, int m0, int c0, float acc[4][4][4])
{
    extern __shared__ __nv_bfloat16 smp[];
    const uint32_t sb0 = smem_to_u32(smp);
    const int tid = threadIdx.x, lane = tid & 31, wid = tid >> 5;
    const int wm = (wid >> 2) * 64, wn = (wid & 3) * 32;
    const int x7 = lane & 7;
    const int arow = (lane & 7) + ((lane >> 3) & 1) * 8;
    const int ak   = lane >> 4;
    const int brow = (lane & 7) + ((lane >> 4) << 3);
    const int bk   = (lane >> 3) & 1;

#pragma unroll
    for (int i = 0; i < 4; i++)
#pragma unroll
        for (int j = 0; j < 4; j++)
#pragma unroll
            for (int r = 0; r < 4; r++) acc[i][j][r] = 0.f;

    const int nck = K / 32;
    gemm_issue(sb0,          Ah, Al, Bh, Bl, K, m0, c0, 0,  tid);
    gemm_issue(sb0 + STG_G,  Ah, Al, Bh, Bl, K, m0, c0, 32, tid);

    for (int ck = 0; ck < nck; ck++) {
        if (ck + 1 < nck) CP_WAIT1(); else CP_WAIT0();
        __syncthreads();
        if (ck + 2 < nck)
            gemm_issue(sb0 + ((ck + 2) % 3) * STG_G, Ah, Al, Bh, Bl,
                       K, m0, c0, (ck + 2) * 32, tid);

        const uint32_t stA = sb0 + (ck % 3) * STG_G;
        const uint32_t stB = stA + 16384;

#pragma unroll
        for (int ks = 0; ks < 32; ks += 16) {
            const int kc = ks >> 3;
            uint32_t ah[4][4], al[4][4];
#pragma unroll
            for (int mf = 0; mf < 4; mf++) {
                uint32_t ra = stA + (uint32_t)((wm + mf * 16 + arow) * 128 +
                                   (((kc + ak) ^ x7) << 4));
                ldsm4(ah[mf], ra);
                ldsm4(al[mf], ra ^ 64u);
            }
#pragma unroll
            for (int p = 0; p < 2; p++) {
                uint32_t bh4[4], bl4[4];
                uint32_t rb = stB + (uint32_t)((wn + p * 16 + brow) * 128 +
                                   (((kc + bk) ^ x7) << 4));
                ldsm4(bh4, rb);
                ldsm4(bl4, rb ^ 64u);
#pragma unroll
                for (int sub = 0; sub < 2; sub++)
#pragma unroll
                    for (int mf = 0; mf < 4; mf++)
                        mma16816(acc[mf][p * 2 + sub], ah[mf], &bh4[sub * 2]);
#pragma unroll
                for (int sub = 0; sub < 2; sub++)
#pragma unroll
                    for (int mf = 0; mf < 4; mf++)
                        mma16816(acc[mf][p * 2 + sub], ah[mf], &bl4[sub * 2]);
#pragma unroll
                for (int sub = 0; sub < 2; sub++)
#pragma unroll
                    for (int mf = 0; mf < 4; mf++)
                        mma16816(acc[mf][p * 2 + sub], al[mf], &bh4[sub * 2]);
            }
        }
    }
}

// ===========================================================================
// fp16 2-term GEMM core (proj): A single fp16, B fp16 hi/lo.
// Same stage layout; A lo-half granules unused.
// ===========================================================================
__device__ __forceinline__ void proj_issue(
    uint32_t sb, const __half* A, const __half* Bh, const __half* Bl,
    int K, int m0, int c0, int k0, int tid)
{
#pragma unroll
    for (int t = 0; t < 4; t++) {
        int f = tid + t * 256;
        int r = f >> 3, c = f & 7;
        int col = (c & 3) * 8;
        uint32_t dst = sb + (uint32_t)(r * 128 + ((c ^ (r & 7)) << 4));
        if (c < 4) CP16(dst, &A[(size_t)(m0 + r) * K + k0 + col]);
        const __half* sb2 = (c < 4) ? &Bh[(size_t)(c0 + r) * K + k0 + col]
                                    : &Bl[(size_t)(c0 + r) * K + k0 + col];
        CP16(dst + 16384, sb2);
    }
    CP_COMMIT();
}

__device__ __forceinline__ void gemm_f16_2t(
    const __half* __restrict__ A,
    const __half* __restrict__ Bh, const __half* __restrict__ Bl,
    int K, int m0, int c0, float acc[4][4][4])
{
    extern __shared__ __nv_bfloat16 smp[];
    const uint32_t sb0 = smem_to_u32(smp);
    const int tid = threadIdx.x, lane = tid & 31, wid = tid >> 5;
    const int wm = (wid >> 2) * 64, wn = (wid & 3) * 32;
    const int x7 = lane & 7;
    const int arow = (lane & 7) + ((lane >> 3) & 1) * 8;
    const int ak   = lane >> 4;
    const int brow = (lane & 7) + ((lane >> 4) << 3);
    const int bk   = (lane >> 3) & 1;

#pragma unroll
    for (int i = 0; i < 4; i++)
#pragma unroll
        for (int j = 0; j < 4; j++)
#pragma unroll
            for (int r = 0; r < 4; r++) acc[i][j][r] = 0.f;

    const int nck = K / 32;
    proj_issue(sb0,          A, Bh, Bl, K, m0, c0, 0,  tid);
    proj_issue(sb0 + STG_G,  A, Bh, Bl, K, m0, c0, 32, tid);

    for (int ck = 0; ck < nck; ck++) {
        if (ck + 1 < nck) CP_WAIT1(); else CP_WAIT0();
        __syncthreads();
        if (ck + 2 < nck)
            proj_issue(sb0 + ((ck + 2) % 3) * STG_G, A, Bh, Bl,
                       K, m0, c0, (ck + 2) * 32, tid);

        const uint32_t stA = sb0 + (ck % 3) * STG_G;
        const uint32_t stB = stA + 16384;

#pragma unroll
        for (int ks = 0; ks < 32; ks += 16) {
            const int kc = ks >> 3;
            uint32_t ah[4][4];
#pragma unroll
            for (int mf = 0; mf < 4; mf++) {
                uint32_t ra = stA + (uint32_t)((wm + mf * 16 + arow) * 128 +
                                   (((kc + ak) ^ x7) << 4));
                ldsm4(ah[mf], ra);
            }
#pragma unroll
            for (int p = 0; p < 2; p++) {
                uint32_t bh4[4], bl4[4];
                uint32_t rb = stB + (uint32_t)((wn + p * 16 + brow) * 128 +
                                   (((kc + bk) ^ x7) << 4));
                ldsm4(bh4, rb);
                ldsm4(bl4, rb ^ 64u);
#pragma unroll
                for (int sub = 0; sub < 2; sub++)
#pragma unroll
                    for (int mf = 0; mf < 4; mf++)
                        mma16816h(acc[mf][p * 2 + sub], ah[mf], &bh4[sub * 2]);
#pragma unroll
                for (int sub = 0; sub < 2; sub++)
#pragma unroll
                    for (int mf = 0; mf < 4; mf++)
                        mma16816h(acc[mf][p * 2 + sub], ah[mf], &bl4[sub * 2]);
            }
        }
    }
}

// ---------------------------------------------------------------------------
// QKV GEMM + scale/RoPE(table) epilogue; V stored transposed as fp16 hi/lo.
// ---------------------------------------------------------------------------
__global__ __launch_bounds__(256, 2) void qkv_mma_kernel()
{
    const int m0 = blockIdx.y * 128, c0 = blockIdx.x * 128;
    float acc[4][4][4];
    gemm_bf16(g_xh, g_xl, g_wqh, g_wql, CH, m0, c0, acc);

    const int tid = threadIdx.x, lane = tid & 31, wid = tid >> 5;
    const int wm = (wid >> 2) * 64, wn = (wid & 3) * 32;
    const int g = lane >> 2, t2 = (lane & 3) * 2;

    const int which = (c0 + wn) / CH;
    const float sc = (which == 0) ? 0.125f : 1.0f;

#pragma unroll
    for (int nf = 0; nf < 4; nf++) {
        const int col = c0 + wn + nf * 8 + t2;
        const int h   = (col % CH) >> 6;
        const int dd  = col & 63;                 // even
#pragma unroll
        for (int mf = 0; mf < 4; mf++) {
#pragma unroll
            for (int rr = 0; rr < 2; rr++) {
                const int m = m0 + wm + mf * 16 + g + rr * 8;
                const int b = m >> 11, n = m & 2047;
                const int bh = b * NH + h;
                float x0 = acc[mf][nf][rr * 2], x1 = acc[mf][nf][rr * 2 + 1];
                if (which == 2) {
                    __half h0 = __float2half_rn(x0);
                    __half h1 = __float2half_rn(x1);
                    size_t o0 = ((size_t)bh * HD + dd) * SEQ + n;
                    g_vth[o0]       = h0;
                    g_vth[o0 + SEQ] = h1;
                    g_vtl[o0]       = __float2half_rn(x0 - __half2float(h0));
                    g_vtl[o0 + SEQ] = __float2half_rn(x1 - __half2float(h1));
                } else {
                    const float2 cs = g_rope[(n << 5) + (dd >> 1)];
                    x0 *= sc; x1 *= sc;
                    uint32_t hi, lo;
                    splitpair(x0 * cs.x - x1 * cs.y, x1 * cs.x + x0 * cs.y, hi, lo);
                    size_t o = ((size_t)bh * SEQ + n) * HD + dd;
                    if (which == 0) {
                        *(uint32_t*)&g_qh[o] = hi; *(uint32_t*)&g_ql[o] = lo;
                    } else {
                        *(uint32_t*)&g_kh[o] = hi; *(uint32_t*)&g_kl[o] = lo;
                    }
                }
            }
        }
    }
}

// ===========================================================================
// Flash attention: bf16 3-term S, fp16 2-term PV (P single fp16).
// ===========================================================================
#define STG_F 32768

__device__ __forceinline__ void flash_issue(uint32_t sb, int bh, int j0, int tid)
{
#pragma unroll
    for (int t = 0; t < 2; t++) {
        int f = tid + t * 256;
        int r = f >> 3, c = f & 7;
        int col = c * 8;
        uint32_t off = (uint32_t)(r * 128 + ((c ^ (r & 7)) << 4));
        CP16(sb + off,         &g_kh[((size_t)bh * SEQ + j0 + r) * HD + col]);
        CP16(sb + 8192 + off,  &g_kl[((size_t)bh * SEQ + j0 + r) * HD + col]);
        CP16(sb + 16384 + off, &g_vth[((size_t)bh * HD + r) * SEQ + j0 + col]);
        CP16(sb + 24576 + off, &g_vtl[((size_t)bh * HD + r) * SEQ + j0 + col]);
    }
    CP_COMMIT();
}

__global__ __launch_bounds__(256, 2) void flash_mma_kernel()
{
    extern __shared__ __nv_bfloat16 fsm[];
    const uint32_t sb0 = smem_to_u32(fsm);

    const int tid = threadIdx.x, lane = tid & 31, wid = tid >> 5;
    const int g = lane >> 2, t2 = (lane & 3) * 2;
    const int bh = blockIdx.y;
    const int q0 = blockIdx.x * 128;
    const int qrow = q0 + wid * 16;
    const int x7 = lane & 7;
    const int brow = (lane & 7) + ((lane >> 4) << 3);
    const int bk   = (lane >> 3) & 1;

    uint32_t qa[2][4][4];
#pragma unroll
    for (int hl = 0; hl < 2; hl++) {
        const __nv_bfloat16* Qp = hl ? g_ql : g_qh;
        const size_t r0 = ((size_t)bh * SEQ + qrow + g) * HD;
        const size_t r1 = ((size_t)bh * SEQ + qrow + g + 8) * HD;
#pragma unroll
        for (int t = 0; t < 4; t++) {
            qa[hl][t][0] = *(const uint32_t*)&Qp[r0 + t * 16 + t2];
            qa[hl][t][1] = *(const uint32_t*)&Qp[r1 + t * 16 + t2];
            qa[hl][t][2] = *(const uint32_t*)&Qp[r0 + t * 16 + t2 + 8];
            qa[hl][t][3] = *(const uint32_t*)&Qp[r1 + t * 16 + t2 + 8];
        }
    }

    float o[8][4];
#pragma unroll
    for (int nf = 0; nf < 8; nf++)
#pragma unroll
        for (int r = 0; r < 4; r++) o[nf][r] = 0.f;
    float mi[2] = {-1e30f, -1e30f}, li[2] = {0.f, 0.f};

    const int ntile = SEQ / 64;
    flash_issue(sb0,         bh, 0,  tid);
    flash_issue(sb0 + STG_F, bh, 64, tid);

    for (int jt = 0; jt < ntile; jt++) {
        if (jt + 1 < ntile) CP_WAIT1(); else CP_WAIT0();
        __syncthreads();
        if (jt + 2 < ntile)
            flash_issue(sb0 + ((jt + 2) % 3) * STG_F, bh, (jt + 2) * 64, tid);

        const uint32_t st = sb0 + (jt % 3) * STG_F;
        const uint32_t cKh = st, cKl = st + 8192;
        const uint32_t cVh = st + 16384, cVl = st + 24576;

        // S = Q.K^T (bf16 3-term)
        float s[8][4];
#pragma unroll
        for (int nf = 0; nf < 8; nf++)
#pragma unroll
            for (int r = 0; r < 4; r++) s[nf][r] = 0.f;
#pragma unroll
        for (int t = 0; t < 4; t++) {
#pragma unroll
            for (int p = 0; p < 4; p++) {
                uint32_t kh4[4], kl4[4];
                uint32_t rb = (uint32_t)((p * 16 + brow) * 128 +
                                         (((2 * t + bk) ^ x7) << 4));
                ldsm4(kh4, cKh + rb);
                ldsm4(kl4, cKl + rb);
#pragma unroll
                for (int sub = 0; sub < 2; sub++) {
                    const int nf = p * 2 + sub;
                    mma16816(s[nf], qa[0][t], &kh4[sub * 2]);
                    mma16816(s[nf], qa[0][t], &kl4[sub * 2]);
                    mma16816(s[nf], qa[1][t], &kh4[sub * 2]);
                }
            }
        }

        // online softmax (rows g, g+8)
#pragma unroll
        for (int rr = 0; rr < 2; rr++) {
            float mx = -1e30f;
#pragma unroll
            for (int nf = 0; nf < 8; nf++)
                mx = fmaxf(mx, fmaxf(s[nf][rr * 2], s[nf][rr * 2 + 1]));
            mx = fmaxf(mx, __shfl_xor_sync(0xffffffffu, mx, 1));
            mx = fmaxf(mx, __shfl_xor_sync(0xffffffffu, mx, 2));
            float mnew = fmaxf(mi[rr], mx);
            float alpha = __expf(mi[rr] - mnew);
            mi[rr] = mnew;
            float sum = 0.f;
#pragma unroll
            for (int nf = 0; nf < 8; nf++) {
                float p0 = __expf(s[nf][rr * 2]     - mnew);
                float p1 = __expf(s[nf][rr * 2 + 1] - mnew);
                s[nf][rr * 2] = p0; s[nf][rr * 2 + 1] = p1;
                sum += p0 + p1;
            }
            sum += __shfl_xor_sync(0xffffffffu, sum, 1);
            sum += __shfl_xor_sync(0xffffffffu, sum, 2);
            li[rr] = li[rr] * alpha + sum;
#pragma unroll
            for (int nf = 0; nf < 8; nf++) {
                o[nf][rr * 2] *= alpha; o[nf][rr * 2 + 1] *= alpha;
            }
        }

        // O += P.V  (P single fp16, V fp16 hi/lo: 2 terms)
#pragma unroll
        for (int t = 0; t < 4; t++) {
            uint32_t ph[4];
            ph[0] = pack_h2(s[2*t][0],   s[2*t][1]);
            ph[1] = pack_h2(s[2*t][2],   s[2*t][3]);
            ph[2] = pack_h2(s[2*t+1][0], s[2*t+1][1]);
            ph[3] = pack_h2(s[2*t+1][2], s[2*t+1][3]);
#pragma unroll
            for (int p = 0; p < 4; p++) {
                uint32_t vh4[4], vl4[4];
                uint32_t rb = (uint32_t)((p * 16 + brow) * 128 +
                                         (((2 * t + bk) ^ x7) << 4));
                ldsm4(vh4, cVh + rb);
                ldsm4(vl4, cVl + rb);
#pragma unroll
                for (int sub = 0; sub < 2; sub++) {
                    const int nf = p * 2 + sub;
                    mma16816h(o[nf], ph, &vh4[sub * 2]);
                    mma16816h(o[nf], ph, &vl4[sub * 2]);
                }
            }
        }
    }

    // epilogue: normalize, write ctx single fp16 [B][N][C]
    const int b = bh / NH, h = bh % NH;
    const float inv0 = 1.f / li[0], inv1 = 1.f / li[1];
#pragma unroll
    for (int rr = 0; rr < 2; rr++) {
        const int n = qrow + g + rr * 8;
        const float inv = rr ? inv1 : inv0;
        const size_t base = ((size_t)b * SEQ + n) * CH + h * HD;
#pragma unroll
        for (int nf = 0; nf < 8; nf++)
            *(uint32_t*)&g_ctxf[base + nf * 8 + t2] =
                pack_h2(o[nf][rr * 2] * inv, o[nf][rr * 2 + 1] * inv);
    }
}

// ---------------------------------------------------------------------------
// Output projection GEMM (fp16 2-term) + bias
// ---------------------------------------------------------------------------
__global__ __launch_bounds__(256, 2) void proj_mma_kernel(
    const float* __restrict__ bias, float* __restrict__ out)
{
    const int m0 = blockIdx.y * 128, c0 = blockIdx.x * 128;
    float acc[4][4][4];
    gemm_f16_2t(g_ctxf, g_wph, g_wpl, CH, m0, c0, acc);

    const int tid = threadIdx.x, lane = tid & 31, wid = tid >> 5;
    const int wm = (wid >> 2) * 64, wn = (wid & 3) * 32;
    const int g = lane >> 2, t2 = (lane & 3) * 2;

#pragma unroll
    for (int nf = 0; nf < 4; nf++) {
        const int col = c0 + wn + nf * 8 + t2;
        const float2 bv = *(const float2*)&bias[col];
#pragma unroll
        for (int mf = 0; mf < 4; mf++) {
#pragma unroll
            for (int rr = 0; rr < 2; rr++) {
                const int m = m0 + wm + mf * 16 + g + rr * 8;
                *(float2*)&out[(size_t)m * CH + col] =
                    make_float2(acc[mf][nf][rr * 2]     + bv.x,
                                acc[mf][nf][rr * 2 + 1] + bv.y);
            }
        }
    }
}

// ---------------------------------------------------------------------------
extern "C" void kernel_launch(void* const* d_in, const int* in_sizes, int n_in,
                              void* d_out, int out_size)
{
    const float* x      = (const float*)d_in[0];
    const float* w_qkv  = (const float*)d_in[1];
    const float* w_proj = (const float*)d_in[2];
    const float* b_proj = (const float*)d_in[3];
    float* out = (float*)d_out;

    const int gemm_smem  = 3 * STG_G;   // 98304
    const int flash_smem = 3 * STG_F;   // 98304
    cudaFuncSetAttribute(qkv_mma_kernel,
                         cudaFuncAttributeMaxDynamicSharedMemorySize, gemm_smem);
    cudaFuncSetAttribute(proj_mma_kernel,
                         cudaFuncAttributeMaxDynamicSharedMemorySize, gemm_smem);
    cudaFuncSetAttribute(flash_mma_kernel,
                         cudaFuncAttributeMaxDynamicSharedMemorySize, flash_smem);

    __nv_bfloat16 *p_xh, *p_xl, *p_wqh, *p_wql;
    __half *p_wph, *p_wpl;
    cudaGetSymbolAddress((void**)&p_xh,  g_xh);
    cudaGetSymbolAddress((void**)&p_xl,  g_xl);
    cudaGetSymbolAddress((void**)&p_wqh, g_wqh);
    cudaGetSymbolAddress((void**)&p_wql, g_wql);
    cudaGetSymbolAddress((void**)&p_wph, g_wph);
    cudaGetSymbolAddress((void**)&p_wpl, g_wpl);

    // launch order: qkv is 4th launch (1-based) -> ncu -s window profiles it
    split_kernel<<<(MROWS*CH/4 + 255)/256, 256>>>(x, p_xh, p_xl, MROWS*CH/4);
    split_kernel<<<(QKVN*CH/4  + 255)/256, 256>>>(w_qkv, p_wqh, p_wql, QKVN*CH/4);
    rope_kernel<<<(SEQ*32 + 255)/256, 256>>>();

    dim3 g1(QKVN / 128, MROWS / 128);   // 18 x 32
    qkv_mma_kernel<<<g1, 256, gemm_smem>>>();

    dim3 g2(SEQ / 128, BB * NH);        // 16 x 24
    flash_mma_kernel<<<g2, 256, flash_smem>>>();

    // wp split only needed by proj; placed here to keep qkv at launch #4
    split_kernel_f16<<<(CH*CH/4 + 255)/256, 256>>>(w_proj, p_wph, p_wpl, CH*CH/4);

    dim3 g3(CH / 128, MROWS / 128);     // 6 x 32
    proj_mma_kernel<<<g3, 256, gemm_smem>>>(b_proj, out);
}

// round 16
// speedup vs baseline: 1.3970x; 1.0995x over previous
#include <cuda_runtime.h>
#include <cuda_bf16.h>
#include <cuda_fp16.h>
#include <math.h>
#include <stdint.h>

#define BB   2
#define SEQ  2048
#define CH   768
#define NH   12
#define HD   64
#define MROWS (BB*SEQ)      // 4096
#define QKVN  (3*CH)        // 2304

// ---- device global scratch ----
__device__ __align__(16) __nv_bfloat16 g_xh[MROWS*CH],  g_xl[MROWS*CH];
__device__ __align__(16) __nv_bfloat16 g_wqh[QKVN*CH],  g_wql[QKVN*CH];
__device__ __align__(16) __half        g_wph[CH*CH],    g_wpl[CH*CH];
__device__ __align__(16) __half        g_qf[BB*NH*SEQ*HD];                 // Q single fp16
__device__ __align__(16) __half        g_kh[BB*NH*SEQ*HD], g_kl[BB*NH*SEQ*HD]; // K fp16 hi/lo
__device__ __align__(16) __half        g_vth[BB*NH*HD*SEQ], g_vtl[BB*NH*HD*SEQ];
__device__ __align__(16) __half        g_ctxf[MROWS*CH];
__device__ __align__(16) float2 g_rope[SEQ * 32];   // [n][dd/2] = (cos, sin)

// ===========================================================================
// helpers
// ===========================================================================
__device__ __forceinline__ uint32_t smem_to_u32(const void* p) {
    uint32_t a;
    asm("{ .reg .u64 t; cvta.to.shared.u64 t, %1; cvt.u32.u64 %0, t; }"
        : "=r"(a) : "l"(p));
    return a;
}
#define CP16(s, g) \
    asm volatile("cp.async.cg.shared.global [%0], [%1], 16;" :: "r"(s), "l"(g))
#define CP_COMMIT() asm volatile("cp.async.commit_group;" ::: "memory")
#define CP_WAIT1()  asm volatile("cp.async.wait_group 1;" ::: "memory")
#define CP_WAIT0()  asm volatile("cp.async.wait_group 0;" ::: "memory")

__device__ __forceinline__ void mma16816(float* c, const uint32_t* a,
                                         const uint32_t* b) {
    asm("mma.sync.aligned.m16n8k16.row.col.f32.bf16.bf16.f32 "
        "{%0,%1,%2,%3}, {%4,%5,%6,%7}, {%8,%9}, {%0,%1,%2,%3};"
        : "+f"(c[0]), "+f"(c[1]), "+f"(c[2]), "+f"(c[3])
        : "r"(a[0]), "r"(a[1]), "r"(a[2]), "r"(a[3]), "r"(b[0]), "r"(b[1]));
}
__device__ __forceinline__ void mma16816h(float* c, const uint32_t* a,
                                          const uint32_t* b) {
    asm("mma.sync.aligned.m16n8k16.row.col.f32.f16.f16.f32 "
        "{%0,%1,%2,%3}, {%4,%5,%6,%7}, {%8,%9}, {%0,%1,%2,%3};"
        : "+f"(c[0]), "+f"(c[1]), "+f"(c[2]), "+f"(c[3])
        : "r"(a[0]), "r"(a[1]), "r"(a[2]), "r"(a[3]), "r"(b[0]), "r"(b[1]));
}
__device__ __forceinline__ void ldsm4(uint32_t r[4], uint32_t a) {
    asm volatile("ldmatrix.sync.aligned.m8n8.x4.shared.b16 {%0,%1,%2,%3}, [%4];"
        : "=r"(r[0]), "=r"(r[1]), "=r"(r[2]), "=r"(r[3]) : "r"(a));
}
__device__ __forceinline__ void splitpair(float x, float y,
                                          uint32_t& hi, uint32_t& lo) {
    __nv_bfloat16 hx = __float2bfloat16_rn(x), hy = __float2bfloat16_rn(y);
    __nv_bfloat162 h = __halves2bfloat162(hx, hy);
    hi = *(uint32_t*)&h;
    __nv_bfloat162 l = __floats2bfloat162_rn(x - __bfloat162float(hx),
                                             y - __bfloat162float(hy));
    lo = *(uint32_t*)&l;
}
__device__ __forceinline__ void splitpairh(float x, float y,
                                           uint32_t& hi, uint32_t& lo) {
    __half hx = __float2half_rn(x), hy = __float2half_rn(y);
    __half2 h = __halves2half2(hx, hy);
    hi = *(uint32_t*)&h;
    __half2 l = __floats2half2_rn(x - __half2float(hx), y - __half2float(hy));
    lo = *(uint32_t*)&l;
}
__device__ __forceinline__ uint32_t pack_h2(float x, float y) {
    __half2 h = __floats2half2_rn(x, y);
    return *(uint32_t*)&h;
}

// ---------------------------------------------------------------------------
// Pre-passes
// ---------------------------------------------------------------------------
__global__ void split_kernel(const float* __restrict__ src,
                             __nv_bfloat16* __restrict__ h,
                             __nv_bfloat16* __restrict__ l, int n4)
{
    int i = blockIdx.x * blockDim.x + threadIdx.x;
    if (i < n4) {
        float4 v = ((const float4*)src)[i];
        uint2 hi, lo;
        splitpair(v.x, v.y, hi.x, lo.x);
        splitpair(v.z, v.w, hi.y, lo.y);
        ((uint2*)h)[i] = hi;
        ((uint2*)l)[i] = lo;
    }
}
__global__ void split_kernel_f16(const float* __restrict__ src,
                                 __half* __restrict__ h,
                                 __half* __restrict__ l, int n4)
{
    int i = blockIdx.x * blockDim.x + threadIdx.x;
    if (i < n4) {
        float4 v = ((const float4*)src)[i];
        uint2 hi, lo;
        splitpairh(v.x, v.y, hi.x, lo.x);
        splitpairh(v.z, v.w, hi.y, lo.y);
        ((uint2*)h)[i] = hi;
        ((uint2*)l)[i] = lo;
    }
}
__global__ void rope_kernel()
{
    int i = blockIdx.x * blockDim.x + threadIdx.x;
    if (i < SEQ * 32) {
        int n = i >> 5, dd2 = i & 31;
        float freq = powf(10000.f, -((float)(2 * dd2)) / 64.f);
        float s, c;
        sincosf((float)n * freq, &s, &c);
        g_rope[i] = make_float2(c, s);
    }
}

// ===========================================================================
// bf16 3-term GEMM core (qkv): 3-stage cp.async, XOR-swizzled 128B rows.
// ===========================================================================
#define STG_G 32768

__device__ __forceinline__ void gemm_issue(
    uint32_t sb, const __nv_bfloat16* Ah, const __nv_bfloat16* Al,
    const __nv_bfloat16* Bh, const __nv_bfloat16* Bl,
    int K, int m0, int c0, int k0, int tid)
{
#pragma unroll
    for (int t = 0; t < 4; t++) {
        int f = tid + t * 256;
        int r = f >> 3, c = f & 7;
        int col = (c & 3) * 8;
        uint32_t dst = sb + (uint32_t)(r * 128 + ((c ^ (r & 7)) << 4));
        const __nv_bfloat16* sa = (c < 4) ? &Ah[(size_t)(m0 + r) * K + k0 + col]
                                          : &Al[(size_t)(m0 + r) * K + k0 + col];
        CP16(dst, sa);
        const __nv_bfloat16* sb2 = (c < 4) ? &Bh[(size_t)(c0 + r) * K + k0 + col]
                                           : &Bl[(size_t)(c0 + r) * K + k0 + col];
        CP16(dst + 16384, sb2);
    }
    CP_COMMIT();
}

__device__ __forceinline__ void gemm_bf16(
    const __nv_bfloat16* __restrict__ Ah, const __nv_bfloat16* __restrict__ Al,
    const __nv_bfloat16* __restrict__ Bh, const __nv_bfloat16* __restrict__ Bl,
    int K, int m0, int c0, float acc[4][4][4])
{
    extern __shared__ __nv_bfloat16 smp[];
    const uint32_t sb0 = smem_to_u32(smp);
    const int tid = threadIdx.x, lane = tid & 31, wid = tid >> 5;
    const int wm = (wid >> 2) * 64, wn = (wid & 3) * 32;
    const int x7 = lane & 7;
    const int arow = (lane & 7) + ((lane >> 3) & 1) * 8;
    const int ak   = lane >> 4;
    const int brow = (lane & 7) + ((lane >> 4) << 3);
    const int bk   = (lane >> 3) & 1;

#pragma unroll
    for (int i = 0; i < 4; i++)
#pragma unroll
        for (int j = 0; j < 4; j++)
#pragma unroll
            for (int r = 0; r < 4; r++) acc[i][j][r] = 0.f;

    const int nck = K / 32;
    gemm_issue(sb0,          Ah, Al, Bh, Bl, K, m0, c0, 0,  tid);
    gemm_issue(sb0 + STG_G,  Ah, Al, Bh, Bl, K, m0, c0, 32, tid);

    for (int ck = 0; ck < nck; ck++) {
        if (ck + 1 < nck) CP_WAIT1(); else CP_WAIT0();
        __syncthreads();
        if (ck + 2 < nck)
            gemm_issue(sb0 + ((ck + 2) % 3) * STG_G, Ah, Al, Bh, Bl,
                       K, m0, c0, (ck + 2) * 32, tid);

        const uint32_t stA = sb0 + (ck % 3) * STG_G;
        const uint32_t stB = stA + 16384;

#pragma unroll
        for (int ks = 0; ks < 32; ks += 16) {
            const int kc = ks >> 3;
            uint32_t ah[4][4], al[4][4];
#pragma unroll
            for (int mf = 0; mf < 4; mf++) {
                uint32_t ra = stA + (uint32_t)((wm + mf * 16 + arow) * 128 +
                                   (((kc + ak) ^ x7) << 4));
                ldsm4(ah[mf], ra);
                ldsm4(al[mf], ra ^ 64u);
            }
#pragma unroll
            for (int p = 0; p < 2; p++) {
                uint32_t bh4[4], bl4[4];
                uint32_t rb = stB + (uint32_t)((wn + p * 16 + brow) * 128 +
                                   (((kc + bk) ^ x7) << 4));
                ldsm4(bh4, rb);
                ldsm4(bl4, rb ^ 64u);
#pragma unroll
                for (int sub = 0; sub < 2; sub++)
#pragma unroll
                    for (int mf = 0; mf < 4; mf++)
                        mma16816(acc[mf][p * 2 + sub], ah[mf], &bh4[sub * 2]);
#pragma unroll
                for (int sub = 0; sub < 2; sub++)
#pragma unroll
                    for (int mf = 0; mf < 4; mf++)
                        mma16816(acc[mf][p * 2 + sub], ah[mf], &bl4[sub * 2]);
#pragma unroll
                for (int sub = 0; sub < 2; sub++)
#pragma unroll
                    for (int mf = 0; mf < 4; mf++)
                        mma16816(acc[mf][p * 2 + sub], al[mf], &bh4[sub * 2]);
            }
        }
    }
}

// ===========================================================================
// fp16 2-term GEMM core (proj): A single fp16, B fp16 hi/lo.
// ===========================================================================
__device__ __forceinline__ void proj_issue(
    uint32_t sb, const __half* A, const __half* Bh, const __half* Bl,
    int K, int m0, int c0, int k0, int tid)
{
#pragma unroll
    for (int t = 0; t < 4; t++) {
        int f = tid + t * 256;
        int r = f >> 3, c = f & 7;
        int col = (c & 3) * 8;
        uint32_t dst = sb + (uint32_t)(r * 128 + ((c ^ (r & 7)) << 4));
        if (c < 4) CP16(dst, &A[(size_t)(m0 + r) * K + k0 + col]);
        const __half* sb2 = (c < 4) ? &Bh[(size_t)(c0 + r) * K + k0 + col]
                                    : &Bl[(size_t)(c0 + r) * K + k0 + col];
        CP16(dst + 16384, sb2);
    }
    CP_COMMIT();
}

__device__ __forceinline__ void gemm_f16_2t(
    const __half* __restrict__ A,
    const __half* __restrict__ Bh, const __half* __restrict__ Bl,
    int K, int m0, int c0, float acc[4][4][4])
{
    extern __shared__ __nv_bfloat16 smp[];
    const uint32_t sb0 = smem_to_u32(smp);
    const int tid = threadIdx.x, lane = tid & 31, wid = tid >> 5;
    const int wm = (wid >> 2) * 64, wn = (wid & 3) * 32;
    const int x7 = lane & 7;
    const int arow = (lane & 7) + ((lane >> 3) & 1) * 8;
    const int ak   = lane >> 4;
    const int brow = (lane & 7) + ((lane >> 4) << 3);
    const int bk   = (lane >> 3) & 1;

#pragma unroll
    for (int i = 0; i < 4; i++)
#pragma unroll
        for (int j = 0; j < 4; j++)
#pragma unroll
            for (int r = 0; r < 4; r++) acc[i][j][r] = 0.f;

    const int nck = K / 32;
    proj_issue(sb0,          A, Bh, Bl, K, m0, c0, 0,  tid);
    proj_issue(sb0 + STG_G,  A, Bh, Bl, K, m0, c0, 32, tid);

    for (int ck = 0; ck < nck; ck++) {
        if (ck + 1 < nck) CP_WAIT1(); else CP_WAIT0();
        __syncthreads();
        if (ck + 2 < nck)
            proj_issue(sb0 + ((ck + 2) % 3) * STG_G, A, Bh, Bl,
                       K, m0, c0, (ck + 2) * 32, tid);

        const uint32_t stA = sb0 + (ck % 3) * STG_G;
        const uint32_t stB = stA + 16384;

#pragma unroll
        for (int ks = 0; ks < 32; ks += 16) {
            const int kc = ks >> 3;
            uint32_t ah[4][4];
#pragma unroll
            for (int mf = 0; mf < 4; mf++) {
                uint32_t ra = stA + (uint32_t)((wm + mf * 16 + arow) * 128 +
                                   (((kc + ak) ^ x7) << 4));
                ldsm4(ah[mf], ra);
            }
#pragma unroll
            for (int p = 0; p < 2; p++) {
                uint32_t bh4[4], bl4[4];
                uint32_t rb = stB + (uint32_t)((wn + p * 16 + brow) * 128 +
                                   (((kc + bk) ^ x7) << 4));
                ldsm4(bh4, rb);
                ldsm4(bl4, rb ^ 64u);
#pragma unroll
                for (int sub = 0; sub < 2; sub++)
#pragma unroll
                    for (int mf = 0; mf < 4; mf++)
                        mma16816h(acc[mf][p * 2 + sub], ah[mf], &bh4[sub * 2]);
#pragma unroll
                for (int sub = 0; sub < 2; sub++)
#pragma unroll
                    for (int mf = 0; mf < 4; mf++)
                        mma16816h(acc[mf][p * 2 + sub], ah[mf], &bl4[sub * 2]);
            }
        }
    }
}

// ---------------------------------------------------------------------------
// QKV GEMM + scale/RoPE(table) epilogue.
// Q -> single fp16; K -> fp16 hi/lo; V -> transposed fp16 hi/lo.
// ---------------------------------------------------------------------------
__global__ __launch_bounds__(256, 2) void qkv_mma_kernel()
{
    const int m0 = blockIdx.y * 128, c0 = blockIdx.x * 128;
    float acc[4][4][4];
    gemm_bf16(g_xh, g_xl, g_wqh, g_wql, CH, m0, c0, acc);

    const int tid = threadIdx.x, lane = tid & 31, wid = tid >> 5;
    const int wm = (wid >> 2) * 64, wn = (wid & 3) * 32;
    const int g = lane >> 2, t2 = (lane & 3) * 2;

    const int which = (c0 + wn) / CH;
    const float sc = (which == 0) ? 0.125f : 1.0f;

#pragma unroll
    for (int nf = 0; nf < 4; nf++) {
        const int col = c0 + wn + nf * 8 + t2;
        const int h   = (col % CH) >> 6;
        const int dd  = col & 63;                 // even
#pragma unroll
        for (int mf = 0; mf < 4; mf++) {
#pragma unroll
            for (int rr = 0; rr < 2; rr++) {
                const int m = m0 + wm + mf * 16 + g + rr * 8;
                const int b = m >> 11, n = m & 2047;
                const int bh = b * NH + h;
                float x0 = acc[mf][nf][rr * 2], x1 = acc[mf][nf][rr * 2 + 1];
                if (which == 2) {
                    __half h0 = __float2half_rn(x0);
                    __half h1 = __float2half_rn(x1);
                    size_t o0 = ((size_t)bh * HD + dd) * SEQ + n;
                    g_vth[o0]       = h0;
                    g_vth[o0 + SEQ] = h1;
                    g_vtl[o0]       = __float2half_rn(x0 - __half2float(h0));
                    g_vtl[o0 + SEQ] = __float2half_rn(x1 - __half2float(h1));
                } else {
                    const float2 cs = g_rope[(n << 5) + (dd >> 1)];
                    x0 *= sc; x1 *= sc;
                    float r0 = x0 * cs.x - x1 * cs.y;
                    float r1 = x1 * cs.x + x0 * cs.y;
                    size_t o = ((size_t)bh * SEQ + n) * HD + dd;
                    if (which == 0) {
                        *(uint32_t*)&g_qf[o] = pack_h2(r0, r1);
                    } else {
                        uint32_t hi, lo;
                        splitpairh(r0, r1, hi, lo);
                        *(uint32_t*)&g_kh[o] = hi;
                        *(uint32_t*)&g_kl[o] = lo;
                    }
                }
            }
        }
    }
}

// ===========================================================================
// Flash attention: fp16 2-term S (Q single, K hi/lo), fp16 2-term PV.
// ===========================================================================
#define STG_F 32768

__device__ __forceinline__ void flash_issue(uint32_t sb, int bh, int j0, int tid)
{
#pragma unroll
    for (int t = 0; t < 2; t++) {
        int f = tid + t * 256;
        int r = f >> 3, c = f & 7;
        int col = c * 8;
        uint32_t off = (uint32_t)(r * 128 + ((c ^ (r & 7)) << 4));
        CP16(sb + off,         &g_kh[((size_t)bh * SEQ + j0 + r) * HD + col]);
        CP16(sb + 8192 + off,  &g_kl[((size_t)bh * SEQ + j0 + r) * HD + col]);
        CP16(sb + 16384 + off, &g_vth[((size_t)bh * HD + r) * SEQ + j0 + col]);
        CP16(sb + 24576 + off, &g_vtl[((size_t)bh * HD + r) * SEQ + j0 + col]);
    }
    CP_COMMIT();
}

__global__ __launch_bounds__(256, 2) void flash_mma_kernel()
{
    extern __shared__ __nv_bfloat16 fsm[];
    const uint32_t sb0 = smem_to_u32(fsm);

    const int tid = threadIdx.x, lane = tid & 31, wid = tid >> 5;
    const int g = lane >> 2, t2 = (lane & 3) * 2;
    const int bh = blockIdx.y;
    const int q0 = blockIdx.x * 128;
    const int qrow = q0 + wid * 16;
    const int x7 = lane & 7;
    const int brow = (lane & 7) + ((lane >> 4) << 3);
    const int bk   = (lane >> 3) & 1;

    // Q fragments (single fp16), register-resident
    uint32_t qa[4][4];
    {
        const size_t r0 = ((size_t)bh * SEQ + qrow + g) * HD;
        const size_t r1 = ((size_t)bh * SEQ + qrow + g + 8) * HD;
#pragma unroll
        for (int t = 0; t < 4; t++) {
            qa[t][0] = *(const uint32_t*)&g_qf[r0 + t * 16 + t2];
            qa[t][1] = *(const uint32_t*)&g_qf[r1 + t * 16 + t2];
            qa[t][2] = *(const uint32_t*)&g_qf[r0 + t * 16 + t2 + 8];
            qa[t][3] = *(const uint32_t*)&g_qf[r1 + t * 16 + t2 + 8];
        }
    }

    float o[8][4];
#pragma unroll
    for (int nf = 0; nf < 8; nf++)
#pragma unroll
        for (int r = 0; r < 4; r++) o[nf][r] = 0.f;
    float mi[2] = {-1e30f, -1e30f}, li[2] = {0.f, 0.f};

    const int ntile = SEQ / 64;
    flash_issue(sb0,         bh, 0,  tid);
    flash_issue(sb0 + STG_F, bh, 64, tid);

    for (int jt = 0; jt < ntile; jt++) {
        if (jt + 1 < ntile) CP_WAIT1(); else CP_WAIT0();
        __syncthreads();
        if (jt + 2 < ntile)
            flash_issue(sb0 + ((jt + 2) % 3) * STG_F, bh, (jt + 2) * 64, tid);

        const uint32_t st = sb0 + (jt % 3) * STG_F;
        const uint32_t cKh = st, cKl = st + 8192;
        const uint32_t cVh = st + 16384, cVl = st + 24576;

        // S = Q.K^T (fp16 2-term: Qh*Kh + Qh*Kl)
        float s[8][4];
#pragma unroll
        for (int nf = 0; nf < 8; nf++)
#pragma unroll
            for (int r = 0; r < 4; r++) s[nf][r] = 0.f;
#pragma unroll
        for (int t = 0; t < 4; t++) {
#pragma unroll
            for (int p = 0; p < 4; p++) {
                uint32_t kh4[4], kl4[4];
                uint32_t rb = (uint32_t)((p * 16 + brow) * 128 +
                                         (((2 * t + bk) ^ x7) << 4));
                ldsm4(kh4, cKh + rb);
                ldsm4(kl4, cKl + rb);
#pragma unroll
                for (int sub = 0; sub < 2; sub++) {
                    const int nf = p * 2 + sub;
                    mma16816h(s[nf], qa[t], &kh4[sub * 2]);
                    mma16816h(s[nf], qa[t], &kl4[sub * 2]);
                }
            }
        }

        // online softmax (rows g, g+8)
#pragma unroll
        for (int rr = 0; rr < 2; rr++) {
            float mx = -1e30f;
#pragma unroll
            for (int nf = 0; nf < 8; nf++)
                mx = fmaxf(mx, fmaxf(s[nf][rr * 2], s[nf][rr * 2 + 1]));
            mx = fmaxf(mx, __shfl_xor_sync(0xffffffffu, mx, 1));
            mx = fmaxf(mx, __shfl_xor_sync(0xffffffffu, mx, 2));
            float mnew = fmaxf(mi[rr], mx);
            float alpha = __expf(mi[rr] - mnew);
            mi[rr] = mnew;
            float sum = 0.f;
#pragma unroll
            for (int nf = 0; nf < 8; nf++) {
                float p0 = __expf(s[nf][rr * 2]     - mnew);
                float p1 = __expf(s[nf][rr * 2 + 1] - mnew);
                s[nf][rr * 2] = p0; s[nf][rr * 2 + 1] = p1;
                sum += p0 + p1;
            }
            sum += __shfl_xor_sync(0xffffffffu, sum, 1);
            sum += __shfl_xor_sync(0xffffffffu, sum, 2);
            li[rr] = li[rr] * alpha + sum;
#pragma unroll
            for (int nf = 0; nf < 8; nf++) {
                o[nf][rr * 2] *= alpha; o[nf][rr * 2 + 1] *= alpha;
            }
        }

        // O += P.V  (P single fp16, V fp16 hi/lo: 2 terms)
#pragma unroll
        for (int t = 0; t < 4; t++) {
            uint32_t ph[4];
            ph[0] = pack_h2(s[2*t][0],   s[2*t][1]);
            ph[1] = pack_h2(s[2*t][2],   s[2*t][3]);
            ph[2] = pack_h2(s[2*t+1][0], s[2*t+1][1]);
            ph[3] = pack_h2(s[2*t+1][2], s[2*t+1][3]);
#pragma unroll
            for (int p = 0; p < 4; p++) {
                uint32_t vh4[4], vl4[4];
                uint32_t rb = (uint32_t)((p * 16 + brow) * 128 +
                                         (((2 * t + bk) ^ x7) << 4));
                ldsm4(vh4, cVh + rb);
                ldsm4(vl4, cVl + rb);
#pragma unroll
                for (int sub = 0; sub < 2; sub++) {
                    const int nf = p * 2 + sub;
                    mma16816h(o[nf], ph, &vh4[sub * 2]);
                    mma16816h(o[nf], ph, &vl4[sub * 2]);
                }
            }
        }
    }

    // epilogue: normalize, write ctx single fp16 [B][N][C]
    const int b = bh / NH, h = bh % NH;
    const float inv0 = 1.f / li[0], inv1 = 1.f / li[1];
#pragma unroll
    for (int rr = 0; rr < 2; rr++) {
        const int n = qrow + g + rr * 8;
        const float inv = rr ? inv1 : inv0;
        const size_t base = ((size_t)b * SEQ + n) * CH + h * HD;
#pragma unroll
        for (int nf = 0; nf < 8; nf++)
            *(uint32_t*)&g_ctxf[base + nf * 8 + t2] =
                pack_h2(o[nf][rr * 2] * inv, o[nf][rr * 2 + 1] * inv);
    }
}

// ---------------------------------------------------------------------------
// Output projection GEMM (fp16 2-term) + bias
// ---------------------------------------------------------------------------
__global__ __launch_bounds__(256, 2) void proj_mma_kernel(
    const float* __restrict__ bias, float* __restrict__ out)
{
    const int m0 = blockIdx.y * 128, c0 = blockIdx.x * 128;
    float acc[4][4][4];
    gemm_f16_2t(g_ctxf, g_wph, g_wpl, CH, m0, c0, acc);

    const int tid = threadIdx.x, lane = tid & 31, wid = tid >> 5;
    const int wm = (wid >> 2) * 64, wn = (wid & 3) * 32;
    const int g = lane >> 2, t2 = (lane & 3) * 2;

#pragma unroll
    for (int nf = 0; nf < 4; nf++) {
        const int col = c0 + wn + nf * 8 + t2;
        const float2 bv = *(const float2*)&bias[col];
#pragma unroll
        for (int mf = 0; mf < 4; mf++) {
#pragma unroll
            for (int rr = 0; rr < 2; rr++) {
                const int m = m0 + wm + mf * 16 + g + rr * 8;
                *(float2*)&out[(size_t)m * CH + col] =
                    make_float2(acc[mf][nf][rr * 2]     + bv.x,
                                acc[mf][nf][rr * 2 + 1] + bv.y);
            }
        }
    }
}

// ---------------------------------------------------------------------------
extern "C" void kernel_launch(void* const* d_in, const int* in_sizes, int n_in,
                              void* d_out, int out_size)
{
    const float* x      = (const float*)d_in[0];
    const float* w_qkv  = (const float*)d_in[1];
    const float* w_proj = (const float*)d_in[2];
    const float* b_proj = (const float*)d_in[3];
    float* out = (float*)d_out;

    const int gemm_smem  = 3 * STG_G;   // 98304
    const int flash_smem = 3 * STG_F;   // 98304
    cudaFuncSetAttribute(qkv_mma_kernel,
                         cudaFuncAttributeMaxDynamicSharedMemorySize, gemm_smem);
    cudaFuncSetAttribute(proj_mma_kernel,
                         cudaFuncAttributeMaxDynamicSharedMemorySize, gemm_smem);
    cudaFuncSetAttribute(flash_mma_kernel,
                         cudaFuncAttributeMaxDynamicSharedMemorySize, flash_smem);

    __nv_bfloat16 *p_xh, *p_xl, *p_wqh, *p_wql;
    __half *p_wph, *p_wpl;
    cudaGetSymbolAddress((void**)&p_xh,  g_xh);
    cudaGetSymbolAddress((void**)&p_xl,  g_xl);
    cudaGetSymbolAddress((void**)&p_wqh, g_wqh);
    cudaGetSymbolAddress((void**)&p_wql, g_wql);
    cudaGetSymbolAddress((void**)&p_wph, g_wph);
    cudaGetSymbolAddress((void**)&p_wpl, g_wpl);

    // launch order keeps a heavy kernel near slot #4-5 for the ncu -s window
    split_kernel<<<(MROWS*CH/4 + 255)/256, 256>>>(x, p_xh, p_xl, MROWS*CH/4);
    split_kernel<<<(QKVN*CH/4  + 255)/256, 256>>>(w_qkv, p_wqh, p_wql, QKVN*CH/4);
    rope_kernel<<<(SEQ*32 + 255)/256, 256>>>();

    dim3 g1(QKVN / 128, MROWS / 128);   // 18 x 32
    qkv_mma_kernel<<<g1, 256, gemm_smem>>>();

    dim3 g2(SEQ / 128, BB * NH);        // 16 x 24
    flash_mma_kernel<<<g2, 256, flash_smem>>>();

    split_kernel_f16<<<(CH*CH/4 + 255)/256, 256>>>(w_proj, p_wph, p_wpl, CH*CH/4);

    dim3 g3(CH / 128, MROWS / 128);     // 6 x 32
    proj_mma_kernel<<<g3, 256, gemm_smem>>>(b_proj, out);
}

// round 17
// speedup vs baseline: 1.7224x; 1.2329x over previous
#include <cuda_runtime.h>
#include <cuda_bf16.h>
#include <cuda_fp16.h>
#include <math.h>
#include <stdint.h>

#define BB   2
#define SEQ  2048
#define CH   768
#define NH   12
#define HD   64
#define MROWS (BB*SEQ)      // 4096
#define QKVN  (3*CH)        // 2304

// ---- device global scratch ----
__device__ __align__(16) __half g_xf[MROWS*CH];                       // X single fp16
__device__ __align__(16) __half g_wqh[QKVN*CH], g_wql[QKVN*CH];       // W_qkv fp16 hi/lo
__device__ __align__(16) __half g_wph[CH*CH],   g_wpl[CH*CH];         // W_proj fp16 hi/lo
__device__ __align__(16) __half g_qf[BB*NH*SEQ*HD];                   // Q single fp16
__device__ __align__(16) __half g_kh[BB*NH*SEQ*HD], g_kl[BB*NH*SEQ*HD]; // K fp16 hi/lo
__device__ __align__(16) __half g_vtf[BB*NH*HD*SEQ];                  // V^T single fp16
__device__ __align__(16) __half g_ctxf[MROWS*CH];
__device__ __align__(16) float2 g_rope[SEQ * 32];   // [n][dd/2] = (cos, sin)

// ===========================================================================
// helpers
// ===========================================================================
__device__ __forceinline__ uint32_t smem_to_u32(const void* p) {
    uint32_t a;
    asm("{ .reg .u64 t; cvta.to.shared.u64 t, %1; cvt.u32.u64 %0, t; }"
        : "=r"(a) : "l"(p));
    return a;
}
#define CP16(s, g) \
    asm volatile("cp.async.cg.shared.global [%0], [%1], 16;" :: "r"(s), "l"(g))
#define CP_COMMIT() asm volatile("cp.async.commit_group;" ::: "memory")
#define CP_WAIT1()  asm volatile("cp.async.wait_group 1;" ::: "memory")
#define CP_WAIT0()  asm volatile("cp.async.wait_group 0;" ::: "memory")

__device__ __forceinline__ void mma16816h(float* c, const uint32_t* a,
                                          const uint32_t* b) {
    asm("mma.sync.aligned.m16n8k16.row.col.f32.f16.f16.f32 "
        "{%0,%1,%2,%3}, {%4,%5,%6,%7}, {%8,%9}, {%0,%1,%2,%3};"
        : "+f"(c[0]), "+f"(c[1]), "+f"(c[2]), "+f"(c[3])
        : "r"(a[0]), "r"(a[1]), "r"(a[2]), "r"(a[3]), "r"(b[0]), "r"(b[1]));
}
__device__ __forceinline__ void ldsm4(uint32_t r[4], uint32_t a) {
    asm volatile("ldmatrix.sync.aligned.m8n8.x4.shared.b16 {%0,%1,%2,%3}, [%4];"
        : "=r"(r[0]), "=r"(r[1]), "=r"(r[2]), "=r"(r[3]) : "r"(a));
}
__device__ __forceinline__ void splitpairh(float x, float y,
                                           uint32_t& hi, uint32_t& lo) {
    __half hx = __float2half_rn(x), hy = __float2half_rn(y);
    __half2 h = __halves2half2(hx, hy);
    hi = *(uint32_t*)&h;
    __half2 l = __floats2half2_rn(x - __half2float(hx), y - __half2float(hy));
    lo = *(uint32_t*)&l;
}
__device__ __forceinline__ uint32_t pack_h2(float x, float y) {
    __half2 h = __floats2half2_rn(x, y);
    return *(uint32_t*)&h;
}

// ---------------------------------------------------------------------------
// Pre-passes
// ---------------------------------------------------------------------------
__global__ void split_kernel_f16(const float* __restrict__ src,
                                 __half* __restrict__ h,
                                 __half* __restrict__ l, int n4)
{
    int i = blockIdx.x * blockDim.x + threadIdx.x;
    if (i < n4) {
        float4 v = ((const float4*)src)[i];
        uint2 hi, lo;
        splitpairh(v.x, v.y, hi.x, lo.x);
        splitpairh(v.z, v.w, hi.y, lo.y);
        ((uint2*)h)[i] = hi;
        ((uint2*)l)[i] = lo;
    }
}
__global__ void conv_kernel_f16(const float* __restrict__ src,
                                __half* __restrict__ h, int n4)
{
    int i = blockIdx.x * blockDim.x + threadIdx.x;
    if (i < n4) {
        float4 v = ((const float4*)src)[i];
        ((uint2*)h)[i] = make_uint2(pack_h2(v.x, v.y), pack_h2(v.z, v.w));
    }
}
__global__ void rope_kernel()
{
    int i = blockIdx.x * blockDim.x + threadIdx.x;
    if (i < SEQ * 32) {
        int n = i >> 5, dd2 = i & 31;
        float freq = powf(10000.f, -((float)(2 * dd2)) / 64.f);
        float s, c;
        sincosf((float)n * freq, &s, &c);
        g_rope[i] = make_float2(c, s);
    }
}

// ===========================================================================
// fp16 2-term GEMM core: A single fp16, B fp16 hi/lo.
// 3-stage cp.async, XOR-swizzled 128B rows. Stage 32KB (A 16KB | B 16KB).
// ===========================================================================
#define STG_G 32768

__device__ __forceinline__ void gemm_issue(
    uint32_t sb, const __half* A, const __half* Bh, const __half* Bl,
    int K, int m0, int c0, int k0, int tid)
{
#pragma unroll
    for (int t = 0; t < 4; t++) {
        int f = tid + t * 256;
        int r = f >> 3, c = f & 7;
        int col = (c & 3) * 8;
        uint32_t dst = sb + (uint32_t)(r * 128 + ((c ^ (r & 7)) << 4));
        if (c < 4) CP16(dst, &A[(size_t)(m0 + r) * K + k0 + col]);
        const __half* sb2 = (c < 4) ? &Bh[(size_t)(c0 + r) * K + k0 + col]
                                    : &Bl[(size_t)(c0 + r) * K + k0 + col];
        CP16(dst + 16384, sb2);
    }
    CP_COMMIT();
}

__device__ __forceinline__ void gemm_f16_2t(
    const __half* __restrict__ A,
    const __half* __restrict__ Bh, const __half* __restrict__ Bl,
    int K, int m0, int c0, float acc[4][4][4])
{
    extern __shared__ __half smp[];
    const uint32_t sb0 = smem_to_u32(smp);
    const int tid = threadIdx.x, lane = tid & 31, wid = tid >> 5;
    const int wm = (wid >> 2) * 64, wn = (wid & 3) * 32;
    const int x7 = lane & 7;
    const int arow = (lane & 7) + ((lane >> 3) & 1) * 8;
    const int ak   = lane >> 4;
    const int brow = (lane & 7) + ((lane >> 4) << 3);
    const int bk   = (lane >> 3) & 1;

#pragma unroll
    for (int i = 0; i < 4; i++)
#pragma unroll
        for (int j = 0; j < 4; j++)
#pragma unroll
            for (int r = 0; r < 4; r++) acc[i][j][r] = 0.f;

    const int nck = K / 32;
    gemm_issue(sb0,          A, Bh, Bl, K, m0, c0, 0,  tid);
    gemm_issue(sb0 + STG_G,  A, Bh, Bl, K, m0, c0, 32, tid);

    for (int ck = 0; ck < nck; ck++) {
        if (ck + 1 < nck) CP_WAIT1(); else CP_WAIT0();
        __syncthreads();
        if (ck + 2 < nck)
            gemm_issue(sb0 + ((ck + 2) % 3) * STG_G, A, Bh, Bl,
                       K, m0, c0, (ck + 2) * 32, tid);

        const uint32_t stA = sb0 + (ck % 3) * STG_G;
        const uint32_t stB = stA + 16384;

#pragma unroll
        for (int ks = 0; ks < 32; ks += 16) {
            const int kc = ks >> 3;
            uint32_t ah[4][4];
#pragma unroll
            for (int mf = 0; mf < 4; mf++) {
                uint32_t ra = stA + (uint32_t)((wm + mf * 16 + arow) * 128 +
                                   (((kc + ak) ^ x7) << 4));
                ldsm4(ah[mf], ra);
            }
#pragma unroll
            for (int p = 0; p < 2; p++) {
                uint32_t bh4[4], bl4[4];
                uint32_t rb = stB + (uint32_t)((wn + p * 16 + brow) * 128 +
                                   (((kc + bk) ^ x7) << 4));
                ldsm4(bh4, rb);
                ldsm4(bl4, rb ^ 64u);
#pragma unroll
                for (int sub = 0; sub < 2; sub++)
#pragma unroll
                    for (int mf = 0; mf < 4; mf++)
                        mma16816h(acc[mf][p * 2 + sub], ah[mf], &bh4[sub * 2]);
#pragma unroll
                for (int sub = 0; sub < 2; sub++)
#pragma unroll
                    for (int mf = 0; mf < 4; mf++)
                        mma16816h(acc[mf][p * 2 + sub], ah[mf], &bl4[sub * 2]);
            }
        }
    }
}

// ---------------------------------------------------------------------------
// QKV GEMM (fp16 2-term) + scale/RoPE(table) epilogue.
// Q -> single fp16; K -> fp16 hi/lo; V -> transposed single fp16.
// ---------------------------------------------------------------------------
__global__ __launch_bounds__(256, 2) void qkv_mma_kernel()
{
    const int m0 = blockIdx.y * 128, c0 = blockIdx.x * 128;
    float acc[4][4][4];
    gemm_f16_2t(g_xf, g_wqh, g_wql, CH, m0, c0, acc);

    const int tid = threadIdx.x, lane = tid & 31, wid = tid >> 5;
    const int wm = (wid >> 2) * 64, wn = (wid & 3) * 32;
    const int g = lane >> 2, t2 = (lane & 3) * 2;

    const int which = (c0 + wn) / CH;
    const float sc = (which == 0) ? 0.125f : 1.0f;

#pragma unroll
    for (int nf = 0; nf < 4; nf++) {
        const int col = c0 + wn + nf * 8 + t2;
        const int h   = (col % CH) >> 6;
        const int dd  = col & 63;                 // even
#pragma unroll
        for (int mf = 0; mf < 4; mf++) {
#pragma unroll
            for (int rr = 0; rr < 2; rr++) {
                const int m = m0 + wm + mf * 16 + g + rr * 8;
                const int b = m >> 11, n = m & 2047;
                const int bh = b * NH + h;
                float x0 = acc[mf][nf][rr * 2], x1 = acc[mf][nf][rr * 2 + 1];
                if (which == 2) {
                    size_t o0 = ((size_t)bh * HD + dd) * SEQ + n;
                    g_vtf[o0]       = __float2half_rn(x0);
                    g_vtf[o0 + SEQ] = __float2half_rn(x1);
                } else {
                    const float2 cs = g_rope[(n << 5) + (dd >> 1)];
                    x0 *= sc; x1 *= sc;
                    float r0 = x0 * cs.x - x1 * cs.y;
                    float r1 = x1 * cs.x + x0 * cs.y;
                    size_t o = ((size_t)bh * SEQ + n) * HD + dd;
                    if (which == 0) {
                        *(uint32_t*)&g_qf[o] = pack_h2(r0, r1);
                    } else {
                        uint32_t hi, lo;
                        splitpairh(r0, r1, hi, lo);
                        *(uint32_t*)&g_kh[o] = hi;
                        *(uint32_t*)&g_kl[o] = lo;
                    }
                }
            }
        }
    }
}

// ===========================================================================
// Flash attention: fp16 2-term S (Q single, K hi/lo), fp16 1-term PV.
// Stage 24KB: Kh 8KB | Kl 8KB | Vh 8KB. 3 stages = 72KB.
// ===========================================================================
#define STG_F 24576

__device__ __forceinline__ void flash_issue(uint32_t sb, int bh, int j0, int tid)
{
#pragma unroll
    for (int t = 0; t < 2; t++) {
        int f = tid + t * 256;
        int r = f >> 3, c = f & 7;
        int col = c * 8;
        uint32_t off = (uint32_t)(r * 128 + ((c ^ (r & 7)) << 4));
        CP16(sb + off,         &g_kh[((size_t)bh * SEQ + j0 + r) * HD + col]);
        CP16(sb + 8192 + off,  &g_kl[((size_t)bh * SEQ + j0 + r) * HD + col]);
        CP16(sb + 16384 + off, &g_vtf[((size_t)bh * HD + r) * SEQ + j0 + col]);
    }
    CP_COMMIT();
}

__global__ __launch_bounds__(256, 2) void flash_mma_kernel()
{
    extern __shared__ __half fsm[];
    const uint32_t sb0 = smem_to_u32(fsm);

    const int tid = threadIdx.x, lane = tid & 31, wid = tid >> 5;
    const int g = lane >> 2, t2 = (lane & 3) * 2;
    const int bh = blockIdx.y;
    const int q0 = blockIdx.x * 128;
    const int qrow = q0 + wid * 16;
    const int x7 = lane & 7;
    const int brow = (lane & 7) + ((lane >> 4) << 3);
    const int bk   = (lane >> 3) & 1;

    // Q fragments (single fp16), register-resident
    uint32_t qa[4][4];
    {
        const size_t r0 = ((size_t)bh * SEQ + qrow + g) * HD;
        const size_t r1 = ((size_t)bh * SEQ + qrow + g + 8) * HD;
#pragma unroll
        for (int t = 0; t < 4; t++) {
            qa[t][0] = *(const uint32_t*)&g_qf[r0 + t * 16 + t2];
            qa[t][1] = *(const uint32_t*)&g_qf[r1 + t * 16 + t2];
            qa[t][2] = *(const uint32_t*)&g_qf[r0 + t * 16 + t2 + 8];
            qa[t][3] = *(const uint32_t*)&g_qf[r1 + t * 16 + t2 + 8];
        }
    }

    float o[8][4];
#pragma unroll
    for (int nf = 0; nf < 8; nf++)
#pragma unroll
        for (int r = 0; r < 4; r++) o[nf][r] = 0.f;
    float mi[2] = {-1e30f, -1e30f}, li[2] = {0.f, 0.f};

    const int ntile = SEQ / 64;
    flash_issue(sb0,         bh, 0,  tid);
    flash_issue(sb0 + STG_F, bh, 64, tid);

    for (int jt = 0; jt < ntile; jt++) {
        if (jt + 1 < ntile) CP_WAIT1(); else CP_WAIT0();
        __syncthreads();
        if (jt + 2 < ntile)
            flash_issue(sb0 + ((jt + 2) % 3) * STG_F, bh, (jt + 2) * 64, tid);

        const uint32_t st = sb0 + (jt % 3) * STG_F;
        const uint32_t cKh = st, cKl = st + 8192;
        const uint32_t cVh = st + 16384;

        // S = Q.K^T (fp16 2-term)
        float s[8][4];
#pragma unroll
        for (int nf = 0; nf < 8; nf++)
#pragma unroll
            for (int r = 0; r < 4; r++) s[nf][r] = 0.f;
#pragma unroll
        for (int t = 0; t < 4; t++) {
#pragma unroll
            for (int p = 0; p < 4; p++) {
                uint32_t kh4[4], kl4[4];
                uint32_t rb = (uint32_t)((p * 16 + brow) * 128 +
                                         (((2 * t + bk) ^ x7) << 4));
                ldsm4(kh4, cKh + rb);
                ldsm4(kl4, cKl + rb);
#pragma unroll
                for (int sub = 0; sub < 2; sub++) {
                    const int nf = p * 2 + sub;
                    mma16816h(s[nf], qa[t], &kh4[sub * 2]);
                    mma16816h(s[nf], qa[t], &kl4[sub * 2]);
                }
            }
        }

        // online softmax (rows g, g+8)
#pragma unroll
        for (int rr = 0; rr < 2; rr++) {
            float mx = -1e30f;
#pragma unroll
            for (int nf = 0; nf < 8; nf++)
                mx = fmaxf(mx, fmaxf(s[nf][rr * 2], s[nf][rr * 2 + 1]));
            mx = fmaxf(mx, __shfl_xor_sync(0xffffffffu, mx, 1));
            mx = fmaxf(mx, __shfl_xor_sync(0xffffffffu, mx, 2));
            float mnew = fmaxf(mi[rr], mx);
            float alpha = __expf(mi[rr] - mnew);
            mi[rr] = mnew;
            float sum = 0.f;
#pragma unroll
            for (int nf = 0; nf < 8; nf++) {
                float p0 = __expf(s[nf][rr * 2]     - mnew);
                float p1 = __expf(s[nf][rr * 2 + 1] - mnew);
                s[nf][rr * 2] = p0; s[nf][rr * 2 + 1] = p1;
                sum += p0 + p1;
            }
            sum += __shfl_xor_sync(0xffffffffu, sum, 1);
            sum += __shfl_xor_sync(0xffffffffu, sum, 2);
            li[rr] = li[rr] * alpha + sum;
#pragma unroll
            for (int nf = 0; nf < 8; nf++) {
                o[nf][rr * 2] *= alpha; o[nf][rr * 2 + 1] *= alpha;
            }
        }

        // O += P.V  (P single fp16, V single fp16: 1 term)
#pragma unroll
        for (int t = 0; t < 4; t++) {
            uint32_t ph[4];
            ph[0] = pack_h2(s[2*t][0],   s[2*t][1]);
            ph[1] = pack_h2(s[2*t][2],   s[2*t][3]);
            ph[2] = pack_h2(s[2*t+1][0], s[2*t+1][1]);
            ph[3] = pack_h2(s[2*t+1][2], s[2*t+1][3]);
#pragma unroll
            for (int p = 0; p < 4; p++) {
                uint32_t vh4[4];
                uint32_t rb = (uint32_t)((p * 16 + brow) * 128 +
                                         (((2 * t + bk) ^ x7) << 4));
                ldsm4(vh4, cVh + rb);
#pragma unroll
                for (int sub = 0; sub < 2; sub++)
                    mma16816h(o[p * 2 + sub], ph, &vh4[sub * 2]);
            }
        }
    }

    // epilogue: normalize, write ctx single fp16 [B][N][C]
    const int b = bh / NH, h = bh % NH;
    const float inv0 = 1.f / li[0], inv1 = 1.f / li[1];
#pragma unroll
    for (int rr = 0; rr < 2; rr++) {
        const int n = qrow + g + rr * 8;
        const float inv = rr ? inv1 : inv0;
        const size_t base = ((size_t)b * SEQ + n) * CH + h * HD;
#pragma unroll
        for (int nf = 0; nf < 8; nf++)
            *(uint32_t*)&g_ctxf[base + nf * 8 + t2] =
                pack_h2(o[nf][rr * 2] * inv, o[nf][rr * 2 + 1] * inv);
    }
}

// ---------------------------------------------------------------------------
// Output projection GEMM (fp16 2-term) + bias
// ---------------------------------------------------------------------------
__global__ __launch_bounds__(256, 2) void proj_mma_kernel(
    const float* __restrict__ bias, float* __restrict__ out)
{
    const int m0 = blockIdx.y * 128, c0 = blockIdx.x * 128;
    float acc[4][4][4];
    gemm_f16_2t(g_ctxf, g_wph, g_wpl, CH, m0, c0, acc);

    const int tid = threadIdx.x, lane = tid & 31, wid = tid >> 5;
    const int wm = (wid >> 2) * 64, wn = (wid & 3) * 32;
    const int g = lane >> 2, t2 = (lane & 3) * 2;

#pragma unroll
    for (int nf = 0; nf < 4; nf++) {
        const int col = c0 + wn + nf * 8 + t2;
        const float2 bv = *(const float2*)&bias[col];
#pragma unroll
        for (int mf = 0; mf < 4; mf++) {
#pragma unroll
            for (int rr = 0; rr < 2; rr++) {
                const int m = m0 + wm + mf * 16 + g + rr * 8;
                *(float2*)&out[(size_t)m * CH + col] =
                    make_float2(acc[mf][nf][rr * 2]     + bv.x,
                                acc[mf][nf][rr * 2 + 1] + bv.y);
            }
        }
    }
}

// ---------------------------------------------------------------------------
extern "C" void kernel_launch(void* const* d_in, const int* in_sizes, int n_in,
                              void* d_out, int out_size)
{
    const float* x      = (const float*)d_in[0];
    const float* w_qkv  = (const float*)d_in[1];
    const float* w_proj = (const float*)d_in[2];
    const float* b_proj = (const float*)d_in[3];
    float* out = (float*)d_out;

    const int gemm_smem  = 3 * STG_G;   // 98304
    const int flash_smem = 3 * STG_F;   // 73728
    cudaFuncSetAttribute(qkv_mma_kernel,
                         cudaFuncAttributeMaxDynamicSharedMemorySize, gemm_smem);
    cudaFuncSetAttribute(proj_mma_kernel,
                         cudaFuncAttributeMaxDynamicSharedMemorySize, gemm_smem);
    cudaFuncSetAttribute(flash_mma_kernel,
                         cudaFuncAttributeMaxDynamicSharedMemorySize, flash_smem);

    __half *p_xf, *p_wqh, *p_wql, *p_wph, *p_wpl;
    cudaGetSymbolAddress((void**)&p_xf,  g_xf);
    cudaGetSymbolAddress((void**)&p_wqh, g_wqh);
    cudaGetSymbolAddress((void**)&p_wql, g_wql);
    cudaGetSymbolAddress((void**)&p_wph, g_wph);
    cudaGetSymbolAddress((void**)&p_wpl, g_wpl);

    // pre-passes (launch order keeps qkv at slot #4 for the ncu -s window)
    conv_kernel_f16<<<(MROWS*CH/4 + 255)/256, 256>>>(x, p_xf, MROWS*CH/4);
    split_kernel_f16<<<(QKVN*CH/4 + 255)/256, 256>>>(w_qkv, p_wqh, p_wql, QKVN*CH/4);
    rope_kernel<<<(SEQ*32 + 255)/256, 256>>>();

    dim3 g1(QKVN / 128, MROWS / 128);   // 18 x 32
    qkv_mma_kernel<<<g1, 256, gemm_smem>>>();

    dim3 g2(SEQ / 128, BB * NH);        // 16 x 24
    flash_mma_kernel<<<g2, 256, flash_smem>>>();

    split_kernel_f16<<<(CH*CH/4 + 255)/256, 256>>>(w_proj, p_wph, p_wpl, CH*CH/4);

    dim3 g3(CH / 128, MROWS / 128);     // 6 x 32
    proj_mma_kernel<<<g3, 256, gemm_smem>>>(b_proj, out);
}